// round 11
// baseline (speedup 1.0000x reference)
#include <cuda_runtime.h>
#include <math.h>

#define N_IMG 1024
#define N_LAB 128
#define N_TOT 1152
#define LATENT 512
#define NLABEL 128

typedef unsigned long long u64;

// ---- packed f32x2 helpers (lanewise rn-FMA; bitwise == two scalar fmaf) ----
__device__ __forceinline__ u64 pk2(float lo, float hi) {
    u64 r; asm("mov.b64 %0, {%1, %2};" : "=l"(r) : "f"(lo), "f"(hi)); return r;
}
__device__ __forceinline__ u64 bc2(float x) { return pk2(x, x); }
__device__ __forceinline__ float2 up2(u64 v) {
    float2 f; asm("mov.b64 {%0, %1}, %2;" : "=f"(f.x), "=f"(f.y) : "l"(v)); return f;
}
__device__ __forceinline__ u64 fma2(u64 a, u64 b, u64 c) {
    u64 d; asm("fma.rn.f32x2 %0, %1, %2, %3;" : "=l"(d) : "l"(a), "l"(b), "l"(c)); return d;
}

// ---------------- scratch (device globals; no allocation allowed) ----------
__device__ __align__(16) float d_pool1[N_TOT * 32 * 14 * 14];
__device__ __align__(16) float d_pool2[N_TOT * 3136];
__device__ __align__(16) float d_fc[N_TOT * LATENT];
__device__ __align__(16) float d_rep[N_LAB * LATENT];
__device__ __align__(16) float d_w[LATENT * LATENT];
__device__ __align__(16) float d_w2[32 * 25 * 64];   // conv2 weights [ic][k][oc]
__device__ float d_rhopart[N_LAB];
__device__ float d_rho[1];

__device__ __forceinline__ float sgnf(float x) {
    return (x > 0.f) ? 1.f : ((x < 0.f) ? -1.f : 0.f);
}

__global__ void nop_kernel() {}

// ---------------- one-time conv2 weight transpose: [oc][ic][k] -> [ic][k][oc]
__global__ void transpose_w2_kernel(const float* __restrict__ w) {
    int idx = blockIdx.x * 256 + threadIdx.x;   // 51200 total
    if (idx < 51200) {
        int ic = idx / 1600, rem = idx % 1600;
        int k = rem >> 6, oc = rem & 63;
        d_w2[idx] = w[oc * 800 + ic * 25 + k];
    }
}

// ---------------- conv1 + relu + pool : [N,1,28,28] -> [N,32,14,14] --------
__global__ void conv1_kernel(const float* __restrict__ img, const float* __restrict__ lab,
                             const float* __restrict__ w, const float* __restrict__ b) {
    int n = blockIdx.x;
    const float* src = (n < N_IMG) ? (img + n * 784) : (lab + (n - N_IMG) * 784);
    __shared__ float sin_[32 * 32];
    __shared__ float sw[800];
    __shared__ float sb[32];
    int t = threadIdx.x;
    for (int idx = t; idx < 1024; idx += 256) {
        int y = idx >> 5, x = idx & 31;
        int iy = y - 2, ix = x - 2;
        float v = 0.f;
        if (iy >= 0 && iy < 28 && ix >= 0 && ix < 28) v = src[iy * 28 + ix];
        sin_[idx] = v;
    }
    for (int idx = t; idx < 800; idx += 256) sw[idx] = w[idx];
    if (t < 32) sb[t] = b[t];
    __syncthreads();
    int oc = t >> 3, tp = t & 7;
    float wr[25];
#pragma unroll
    for (int u = 0; u < 25; u++) wr[u] = sw[oc * 25 + u];
    float bias = sb[oc];
    for (int pos = tp; pos < 196; pos += 8) {
        int py = pos / 14, px = pos % 14;
        float win[36];
        int base = (2 * py) * 32 + 2 * px;
#pragma unroll
        for (int wy = 0; wy < 6; wy++)
#pragma unroll
            for (int wx = 0; wx < 6; wx++)
                win[wy * 6 + wx] = sin_[base + wy * 32 + wx];
        u64 pp[6][5];
#pragma unroll
        for (int ky = 0; ky < 6; ky++)
#pragma unroll
            for (int kx = 0; kx < 5; kx++) pp[ky][kx] = pk2(win[ky * 6 + kx], win[ky * 6 + kx + 1]);
        u64 A0 = 0ull, A1 = 0ull;
#pragma unroll
        for (int ky = 0; ky < 5; ky++)
#pragma unroll
            for (int kx = 0; kx < 5; kx++) {
                u64 wp = bc2(wr[ky * 5 + kx]);
                A0 = fma2(wp, pp[ky][kx], A0);
                A1 = fma2(wp, pp[ky + 1][kx], A1);
            }
        float2 f0 = up2(A0), f1 = up2(A1);
        float m = fmaxf(fmaxf(fmaxf(f0.x + bias, 0.f), fmaxf(f0.y + bias, 0.f)),
                        fmaxf(fmaxf(f1.x + bias, 0.f), fmaxf(f1.y + bias, 0.f)));
        d_pool1[n * 6272 + oc * 196 + pos] = m;
    }
}

// ---------------- conv2 + relu + pool : [N,32,14,14] -> [N,64,7,7] ---------
// 392 thr, t = pos*8 + grp: each warp = 4 positions x 8 oc-groups.
// Window LDS.64 -> only 4 distinct addresses/warp (broadcast-dedup, ~1 wf);
// weight LDG.128 -> 8 groups x 16B = one contiguous 128B line (~1 wf).
// Weights from pre-transposed d_w2[ic][k][oc]; no smem staging, one barrier.
// Per-output accumulation order unchanged (ic -> ky -> kx).
__global__ void conv2_kernel(const float* __restrict__ b) {
    int n = blockIdx.x;
    __shared__ float sin_[32 * 18 * 18];  // 10368 floats
    int t = threadIdx.x;                  // 392 threads
    for (int idx = t; idx < 10368; idx += 392) {
        int ic = idx / 324, rem = idx % 324;
        int y = rem / 18, x = rem % 18;
        int iy = y - 2, ix = x - 2;
        float v = 0.f;
        if (iy >= 0 && iy < 14 && ix >= 0 && ix < 14)
            v = d_pool1[n * 6272 + ic * 196 + iy * 14 + ix];
        sin_[idx] = v;
    }
    __syncthreads();                      // the only barrier

    int grp = t & 7, pos = t >> 3;        // FLIPPED: lanes span 8 grps x 4 pos
    int py = pos / 7, px = pos % 7;
    u64 acc[4][4];                        // [oc-pair][subpos 00,01,10,11]
#pragma unroll
    for (int p = 0; p < 4; p++)
#pragma unroll
        for (int q = 0; q < 4; q++) acc[p][q] = 0ull;

    const float* wg = d_w2 + grp * 8;     // [ic][k][oc] slice for this group
    for (int ic = 0; ic < 32; ic++) {
        float win[36];
        int base = ic * 324 + (2 * py) * 18 + 2 * px;   // even -> float2-aligned
#pragma unroll
        for (int wy = 0; wy < 6; wy++) {
            float2 va = *(const float2*)&sin_[base + wy * 18 + 0];
            float2 vb = *(const float2*)&sin_[base + wy * 18 + 2];
            float2 vc = *(const float2*)&sin_[base + wy * 18 + 4];
            win[wy * 6 + 0] = va.x; win[wy * 6 + 1] = va.y;
            win[wy * 6 + 2] = vb.x; win[wy * 6 + 3] = vb.y;
            win[wy * 6 + 4] = vc.x; win[wy * 6 + 5] = vc.y;
        }
        const float* wic = wg + ic * 1600;
#pragma unroll
        for (int ky = 0; ky < 5; ky++)
#pragma unroll
            for (int kx = 0; kx < 5; kx++) {
                const float* swk = wic + (ky * 5 + kx) * 64;   // 16B-aligned
                ulonglong2 wp01 = *(const ulonglong2*)&swk[0];
                ulonglong2 wp23 = *(const ulonglong2*)&swk[4];
                u64 wp0 = wp01.x, wp1 = wp01.y, wp2 = wp23.x, wp3 = wp23.y;
                u64 b00 = bc2(win[ky * 6 + kx]);
                u64 b01 = bc2(win[ky * 6 + kx + 1]);
                u64 b10 = bc2(win[(ky + 1) * 6 + kx]);
                u64 b11 = bc2(win[(ky + 1) * 6 + kx + 1]);
                acc[0][0] = fma2(wp0, b00, acc[0][0]);
                acc[0][1] = fma2(wp0, b01, acc[0][1]);
                acc[0][2] = fma2(wp0, b10, acc[0][2]);
                acc[0][3] = fma2(wp0, b11, acc[0][3]);
                acc[1][0] = fma2(wp1, b00, acc[1][0]);
                acc[1][1] = fma2(wp1, b01, acc[1][1]);
                acc[1][2] = fma2(wp1, b10, acc[1][2]);
                acc[1][3] = fma2(wp1, b11, acc[1][3]);
                acc[2][0] = fma2(wp2, b00, acc[2][0]);
                acc[2][1] = fma2(wp2, b01, acc[2][1]);
                acc[2][2] = fma2(wp2, b10, acc[2][2]);
                acc[2][3] = fma2(wp2, b11, acc[2][3]);
                acc[3][0] = fma2(wp3, b00, acc[3][0]);
                acc[3][1] = fma2(wp3, b01, acc[3][1]);
                acc[3][2] = fma2(wp3, b10, acc[3][2]);
                acc[3][3] = fma2(wp3, b11, acc[3][3]);
            }
    }
#pragma unroll
    for (int p = 0; p < 4; p++) {
        int oc0 = grp * 8 + 2 * p;
        float bias0 = b[oc0], bias1 = b[oc0 + 1];
        float2 v0 = up2(acc[p][0]), v1 = up2(acc[p][1]);
        float2 v2 = up2(acc[p][2]), v3 = up2(acc[p][3]);
        float m0 = fmaxf(fmaxf(fmaxf(v0.x + bias0, 0.f), fmaxf(v1.x + bias0, 0.f)),
                         fmaxf(fmaxf(v2.x + bias0, 0.f), fmaxf(v3.x + bias0, 0.f)));
        float m1 = fmaxf(fmaxf(fmaxf(v0.y + bias1, 0.f), fmaxf(v1.y + bias1, 0.f)),
                         fmaxf(fmaxf(v2.y + bias1, 0.f), fmaxf(v3.y + bias1, 0.f)));
        d_pool2[n * 3136 + oc0 * 49 + pos] = m0;
        d_pool2[n * 3136 + (oc0 + 1) * 49 + pos] = m1;
    }
}

// ---------------- fc1: [1152,3136] @ [512,3136]^T + b -> d_fc --------------
__global__ void fc1_kernel(const float* __restrict__ fw, const float* __restrict__ fb) {
    __shared__ float As[32][66];
    __shared__ float Bs[32][66];
    int t = threadIdx.x;
    int tx = t & 15, ty = t >> 4;
    int m0 = blockIdx.x * 64;
    int n0 = blockIdx.y * 64;
    u64 acc[4][2];
#pragma unroll
    for (int i = 0; i < 4; i++) { acc[i][0] = 0ull; acc[i][1] = 0ull; }

    for (int k0 = 0; k0 < 3136; k0 += 32) {
        __syncthreads();
        for (int id = t; id < 512; id += 256) {
            int row = id >> 3, kk4 = id & 7;
            float4 v = *(const float4*)&d_pool2[(m0 + row) * 3136 + k0 + kk4 * 4];
            As[kk4 * 4 + 0][row] = v.x;
            As[kk4 * 4 + 1][row] = v.y;
            As[kk4 * 4 + 2][row] = v.z;
            As[kk4 * 4 + 3][row] = v.w;
        }
        for (int id = t; id < 512; id += 256) {
            int row = id >> 3, kk4 = id & 7;
            float4 v = *(const float4*)&fw[(n0 + row) * 3136 + k0 + kk4 * 4];
            Bs[kk4 * 4 + 0][row] = v.x;
            Bs[kk4 * 4 + 1][row] = v.y;
            Bs[kk4 * 4 + 2][row] = v.z;
            Bs[kk4 * 4 + 3][row] = v.w;
        }
        __syncthreads();
#pragma unroll
        for (int kk = 0; kk < 32; kk++) {
            u64 b01 = *(const u64*)&Bs[kk][tx * 4];
            u64 b23 = *(const u64*)&Bs[kk][tx * 4 + 2];
#pragma unroll
            for (int i = 0; i < 4; i++) {
                u64 ap = bc2(As[kk][ty * 4 + i]);
                acc[i][0] = fma2(ap, b01, acc[i][0]);
                acc[i][1] = fma2(ap, b23, acc[i][1]);
            }
        }
    }
#pragma unroll
    for (int i = 0; i < 4; i++) {
        int m = m0 + ty * 4 + i;
        float2 c01 = up2(acc[i][0]), c23 = up2(acc[i][1]);
        int nn = n0 + tx * 4;
        d_fc[m * 512 + nn + 0] = c01.x + fb[nn + 0];
        d_fc[m * 512 + nn + 1] = c01.y + fb[nn + 1];
        d_fc[m * 512 + nn + 2] = c23.x + fb[nn + 2];
        d_fc[m * 512 + nn + 3] = c23.y + fb[nn + 3];
    }
}

// ---------------- rep = tanh(fc rows 1024..1151) + rho partial sums --------
__global__ void tanh_rep_kernel() {
    int bb = blockIdx.x;
    int t = threadIdx.x;
    float v = tanhf(d_fc[(N_IMG + bb) * LATENT + t]);
    d_rep[bb * LATENT + t] = v;
    float s = v;
#pragma unroll
    for (int off = 16; off > 0; off >>= 1) s += __shfl_down_sync(0xffffffffu, s, off);
    __shared__ float ws[16];
    if ((t & 31) == 0) ws[t >> 5] = s;
    __syncthreads();
    if (t == 0) {
        float tot = 0.f;
        for (int i = 0; i < 16; i++) tot += ws[i];
        d_rhopart[bb] = tot;
    }
}

__global__ void rho_kernel() {
    if (threadIdx.x == 0) {
        float s = 0.f;
        for (int i = 0; i < 128; i++) s += d_rhopart[i];
        d_rho[0] = s / 65536.0f;
    }
}

// ---------------- Hopfield W = ((rep-rho)^T (rep-rho)) * (1-I) / 128 -------
__global__ void hopw_kernel() {
    __shared__ float ti[128][32];
    __shared__ float tj[128][32];
    float rho = d_rho[0];
    int i0 = blockIdx.x * 32, j0 = blockIdx.y * 32;
    int t = threadIdx.x;
    for (int idx = t; idx < 4096; idx += 256) {
        int bb = idx >> 5, c = idx & 31;
        ti[bb][c] = d_rep[bb * 512 + i0 + c] - rho;
        tj[bb][c] = d_rep[bb * 512 + j0 + c] - rho;
    }
    __syncthreads();
    int tx = t & 15, ty = t >> 4;
    float a00 = 0.f, a01 = 0.f, a10 = 0.f, a11 = 0.f;
    for (int bb = 0; bb < 128; bb++) {
        float x0 = ti[bb][tx * 2], x1 = ti[bb][tx * 2 + 1];
        float y0 = tj[bb][ty * 2], y1 = tj[bb][ty * 2 + 1];
        a00 = fmaf(x0, y0, a00); a01 = fmaf(x0, y1, a01);
        a10 = fmaf(x1, y0, a10); a11 = fmaf(x1, y1, a11);
    }
    const float inv = 1.f / 128.f;
    int i = i0 + tx * 2, j = j0 + ty * 2;
    d_w[i * 512 + j]             = (i == j)         ? 0.f : a00 * inv;
    d_w[i * 512 + (j + 1)]       = (i == j + 1)     ? 0.f : a01 * inv;
    d_w[(i + 1) * 512 + j]       = (i + 1 == j)     ? 0.f : a10 * inv;
    d_w[(i + 1) * 512 + (j + 1)] = (i + 1 == j + 1) ? 0.f : a11 * inv;
}

// ---------------- label = softmax(lat @ fcn_w^T + fcn_b) -------------------
__global__ void label_kernel(const float* __restrict__ fw, const float* __restrict__ fb,
                             float* __restrict__ out) {
    int blk = blockIdx.x;          // images blk*4 .. blk*4+3
    int l = threadIdx.x;           // 0..127
    int lane = l & 31, warp = l >> 5;
    __shared__ float slat[4][512];
    __shared__ float redm[4], reds[4];
    for (int idx = l; idx < 512; idx += 128) {
        int img = idx >> 7, k4 = idx & 127;
        ((float4*)&slat[img][0])[k4] = ((const float4*)(d_fc + (blk * 4 + img) * 512))[k4];
    }
    __syncthreads();
    float acc[4];
    float bias = fb[l];
#pragma unroll
    for (int img = 0; img < 4; img++) acc[img] = bias;
    const float4* fr = (const float4*)(fw + l * 512);
    for (int kc = 0; kc < 16; kc++) {
        float4 wv[8];
#pragma unroll
        for (int c = 0; c < 8; c++) wv[c] = fr[kc * 8 + c];
#pragma unroll
        for (int img = 0; img < 4; img++) {
            const float4* s4 = (const float4*)&slat[img][kc * 32];
#pragma unroll
            for (int c = 0; c < 8; c++) {
                float4 sv = s4[c];
                acc[img] = fmaf(sv.x, wv[c].x, acc[img]);
                acc[img] = fmaf(sv.y, wv[c].y, acc[img]);
                acc[img] = fmaf(sv.z, wv[c].z, acc[img]);
                acc[img] = fmaf(sv.w, wv[c].w, acc[img]);
            }
        }
    }
    for (int img = 0; img < 4; img++) {
        float m = acc[img];
#pragma unroll
        for (int off = 16; off > 0; off >>= 1)
            m = fmaxf(m, __shfl_xor_sync(0xffffffffu, m, off));
        if (lane == 0) redm[warp] = m;
        __syncthreads();
        m = fmaxf(fmaxf(redm[0], redm[1]), fmaxf(redm[2], redm[3]));
        float ex = expf(acc[img] - m);
        float s = ex;
#pragma unroll
        for (int off = 16; off > 0; off >>= 1)
            s += __shfl_xor_sync(0xffffffffu, s, off);
        if (lane == 0) reds[warp] = s;
        __syncthreads();
        s = reds[0] + reds[1] + reds[2] + reds[3];
        out[131072 + (blk * 4 + img) * 128 + l] = ex / s;
        __syncthreads();
    }
}

// ---------------- Hopfield clustering (sparse union-delta) + softmax -------
__global__ void __launch_bounds__(512, 1) cluster_kernel(float* __restrict__ out) {
    __shared__ float coef[512][8];
    __shared__ int   ulist[512];
    __shared__ int   warpcnt[16], warpbase[16];
    __shared__ int   s_nf, doneflag;
    __shared__ float epart[16][8];
    __shared__ float esm[8];
    __shared__ unsigned wA[16], wB[16];
    __shared__ float dots[8][128];

    int t = threadIdx.x;
    int lane = t & 31, warp = t >> 5;
    int row0 = blockIdx.x * 8;
    const float* wc = d_w + t;

    float h[8], sp[8], sp2[8], mins[8], min_e[8];
    const float nanv = __int_as_float(0x7fffffff);

#pragma unroll
    for (int r = 0; r < 8; r++) {
        float v = tanhf(d_fc[(row0 + r) * 512 + t]);
        sp[r] = v;
        sp2[r] = nanv;
        mins[r] = 0.f;
        min_e[r] = INFINITY;
    }
    *(float4*)&coef[t][0] = make_float4(sp[0], sp[1], sp[2], sp[3]);
    *(float4*)&coef[t][4] = make_float4(sp[4], sp[5], sp[6], sp[7]);
    __syncthreads();

    // prologue full GEMV: h = s0 @ w
    {
        u64 hh[4] = {0ull, 0ull, 0ull, 0ull};
#pragma unroll 4
        for (int j = 0; j < 512; j++) {
            u64 wp = bc2(wc[j * 512]);
            ulonglong2 cA = *(const ulonglong2*)&coef[j][0];
            ulonglong2 cB = *(const ulonglong2*)&coef[j][4];
            hh[0] = fma2(wp, cA.x, hh[0]);
            hh[1] = fma2(wp, cA.y, hh[1]);
            hh[2] = fma2(wp, cB.x, hh[2]);
            hh[3] = fma2(wp, cB.y, hh[3]);
        }
#pragma unroll
        for (int q = 0; q < 4; q++) {
            float2 f = up2(hh[q]);
            h[2 * q] = f.x; h[2 * q + 1] = f.y;
        }
    }

    for (int iter = 0; iter < LATENT; iter++) {
        float sn[8], cf[8];
        unsigned a = 0, b = 0;
        bool flip = false;
#pragma unroll
        for (int r = 0; r < 8; r++) {
            float v = fabsf(sp[r]) * sgnf(h[r]);
            sn[r] = v;
            cf[r] = v - sp[r];
            if (cf[r] != 0.f) flip = true;
            if (v == sp[r]) a |= (1u << r);
            if (v == sp2[r]) b |= (1u << r);
        }
        a = __reduce_and_sync(0xffffffffu, a);
        b = __reduce_and_sync(0xffffffffu, b);
        unsigned bal = __ballot_sync(0xffffffffu, flip);
        if (lane == 0) { wA[warp] = a; wB[warp] = b; warpcnt[warp] = __popc(bal); }
        __syncthreads();   // S1
        *(float4*)&coef[t][0] = make_float4(cf[0], cf[1], cf[2], cf[3]);
        *(float4*)&coef[t][4] = make_float4(cf[4], cf[5], cf[6], cf[7]);
        if (t == 0) {
            int accn = 0;
            unsigned A = 0xffu, B = 0xffu;
            for (int q = 0; q < 16; q++) {
                warpbase[q] = accn;
                accn += warpcnt[q];
                A &= wA[q]; B &= wB[q];
            }
            s_nf = accn;
            doneflag = ((A | B) == 0xffu) ? 1 : 0;
        }
        __syncthreads();   // S2
        if (flip) {
            int rank = __popc(bal & ((1u << lane) - 1u));
            ulist[warpbase[warp] + rank] = t;
        }
        __syncthreads();   // S3
        int nf = s_nf;
        int done = doneflag;

        // delta update: h += coef[j] * w[j][t] over union list
        {
            u64 hh[4];
#pragma unroll
            for (int q = 0; q < 4; q++) hh[q] = pk2(h[2 * q], h[2 * q + 1]);
            int i = 0;
            for (; i + 4 <= nf; i += 4) {
                int j0 = ulist[i], j1 = ulist[i + 1], j2 = ulist[i + 2], j3 = ulist[i + 3];
                float w0 = wc[j0 * 512], w1 = wc[j1 * 512];
                float w2 = wc[j2 * 512], w3 = wc[j3 * 512];
                {
                    u64 wp = bc2(w0);
                    ulonglong2 cA = *(const ulonglong2*)&coef[j0][0];
                    ulonglong2 cB = *(const ulonglong2*)&coef[j0][4];
                    hh[0] = fma2(wp, cA.x, hh[0]); hh[1] = fma2(wp, cA.y, hh[1]);
                    hh[2] = fma2(wp, cB.x, hh[2]); hh[3] = fma2(wp, cB.y, hh[3]);
                }
                {
                    u64 wp = bc2(w1);
                    ulonglong2 cA = *(const ulonglong2*)&coef[j1][0];
                    ulonglong2 cB = *(const ulonglong2*)&coef[j1][4];
                    hh[0] = fma2(wp, cA.x, hh[0]); hh[1] = fma2(wp, cA.y, hh[1]);
                    hh[2] = fma2(wp, cB.x, hh[2]); hh[3] = fma2(wp, cB.y, hh[3]);
                }
                {
                    u64 wp = bc2(w2);
                    ulonglong2 cA = *(const ulonglong2*)&coef[j2][0];
                    ulonglong2 cB = *(const ulonglong2*)&coef[j2][4];
                    hh[0] = fma2(wp, cA.x, hh[0]); hh[1] = fma2(wp, cA.y, hh[1]);
                    hh[2] = fma2(wp, cB.x, hh[2]); hh[3] = fma2(wp, cB.y, hh[3]);
                }
                {
                    u64 wp = bc2(w3);
                    ulonglong2 cA = *(const ulonglong2*)&coef[j3][0];
                    ulonglong2 cB = *(const ulonglong2*)&coef[j3][4];
                    hh[0] = fma2(wp, cA.x, hh[0]); hh[1] = fma2(wp, cA.y, hh[1]);
                    hh[2] = fma2(wp, cB.x, hh[2]); hh[3] = fma2(wp, cB.y, hh[3]);
                }
            }
            for (; i < nf; i++) {
                int j = ulist[i];
                u64 wp = bc2(wc[j * 512]);
                ulonglong2 cA = *(const ulonglong2*)&coef[j][0];
                ulonglong2 cB = *(const ulonglong2*)&coef[j][4];
                hh[0] = fma2(wp, cA.x, hh[0]); hh[1] = fma2(wp, cA.y, hh[1]);
                hh[2] = fma2(wp, cB.x, hh[2]); hh[3] = fma2(wp, cB.y, hh[3]);
            }
#pragma unroll
            for (int q = 0; q < 4; q++) {
                float2 f = up2(hh[q]);
                h[2 * q] = f.x; h[2 * q + 1] = f.y;
            }
        }

        // energy e[r] = -sum_t sn[r]*h[r]
        float p[8];
#pragma unroll
        for (int r = 0; r < 8; r++) p[r] = sn[r] * h[r];
#pragma unroll
        for (int r = 0; r < 8; r++) {
#pragma unroll
            for (int off = 16; off > 0; off >>= 1)
                p[r] += __shfl_down_sync(0xffffffffu, p[r], off);
        }
        if (lane == 0) {
#pragma unroll
            for (int r = 0; r < 8; r++) epart[warp][r] = p[r];
        }
        __syncthreads();   // S4
        if (t < 8) {
            float e = 0.f;
            for (int q = 0; q < 16; q++) e += epart[q][t];
            esm[t] = -e;
        }
        __syncthreads();   // S5
#pragma unroll
        for (int r = 0; r < 8; r++) {
            float e = esm[r];
            if (e < min_e[r]) { min_e[r] = e; mins[r] = sn[r]; }
            sp2[r] = sp[r]; sp[r] = sn[r];
        }
        if (done) break;
    }

    // ---------------- epilogue: out = softmax(|min_s @ rep^T|) -------------
    __syncthreads();
    *(float4*)&coef[t][0] = make_float4(mins[0], mins[1], mins[2], mins[3]);
    *(float4*)&coef[t][4] = make_float4(mins[4], mins[5], mins[6], mins[7]);
    __syncthreads();

    int l = t >> 2, q = t & 3;
#pragma unroll
    for (int r = 0; r < 8; r++) {
        const float4* rp = (const float4*)(d_rep + l * 512 + q * 128);
        float v = 0.f;
#pragma unroll 8
        for (int i4 = 0; i4 < 32; i4++) {
            float4 rv = rp[i4];
            int j = q * 128 + i4 * 4;
            v = fmaf(coef[j + 0][r], rv.x, v);
            v = fmaf(coef[j + 1][r], rv.y, v);
            v = fmaf(coef[j + 2][r], rv.z, v);
            v = fmaf(coef[j + 3][r], rv.w, v);
        }
        v += __shfl_xor_sync(0xffffffffu, v, 1);
        v += __shfl_xor_sync(0xffffffffu, v, 2);
        if (q == 0) dots[r][l] = fabsf(v);
    }
    __syncthreads();

    if (warp < 8) {
        int r = warp;
        float v0 = dots[r][lane], v1 = dots[r][lane + 32];
        float v2 = dots[r][lane + 64], v3 = dots[r][lane + 96];
        float m = fmaxf(fmaxf(v0, v1), fmaxf(v2, v3));
#pragma unroll
        for (int off = 16; off > 0; off >>= 1)
            m = fmaxf(m, __shfl_xor_sync(0xffffffffu, m, off));
        float e0 = expf(v0 - m), e1 = expf(v1 - m), e2 = expf(v2 - m), e3 = expf(v3 - m);
        float s = e0 + e1 + e2 + e3;
#pragma unroll
        for (int off = 16; off > 0; off >>= 1)
            s += __shfl_xor_sync(0xffffffffu, s, off);
        float inv = 1.f / s;
        float* o = out + (row0 + r) * 128;
        o[lane] = e0 * inv;
        o[lane + 32] = e1 * inv;
        o[lane + 64] = e2 * inv;
        o[lane + 96] = e3 * inv;
    }
}

// ---------------------------------------------------------------------------
extern "C" void kernel_launch(void* const* d_in, const int* in_sizes, int n_in,
                              void* d_out, int out_size) {
    const float* image     = (const float*)d_in[0];
    const float* label_img = (const float*)d_in[1];
    const float* c1w       = (const float*)d_in[2];
    const float* c1b       = (const float*)d_in[3];
    const float* c2w       = (const float*)d_in[4];
    const float* c2b       = (const float*)d_in[5];
    const float* f1w       = (const float*)d_in[6];
    const float* f1b       = (const float*)d_in[7];
    const float* fnw       = (const float*)d_in[8];
    const float* fnb       = (const float*)d_in[9];
    float* out = (float*)d_out;

    transpose_w2_kernel<<<200, 256>>>(c2w);
    conv1_kernel<<<N_TOT, 256>>>(image, label_img, c1w, c1b);
    nop_kernel<<<1, 32>>>();      // keep conv2 in the ncu-profiled slot (launch #4)
    conv2_kernel<<<N_TOT, 392>>>(c2b);
    fc1_kernel<<<dim3(18, 8), 256>>>(f1w, f1b);
    label_kernel<<<256, 128>>>(fnw, fnb, out);
    tanh_rep_kernel<<<128, 512>>>();
    rho_kernel<<<1, 32>>>();
    hopw_kernel<<<dim3(16, 16), 256>>>();
    cluster_kernel<<<128, 512>>>(out);
}

// round 12
// speedup vs baseline: 1.1074x; 1.1074x over previous
#include <cuda_runtime.h>
#include <math.h>

#define N_IMG 1024
#define N_LAB 128
#define N_TOT 1152
#define LATENT 512
#define NLABEL 128

typedef unsigned long long u64;

// ---- packed f32x2 helpers (lanewise rn-FMA; bitwise == two scalar fmaf) ----
__device__ __forceinline__ u64 pk2(float lo, float hi) {
    u64 r; asm("mov.b64 %0, {%1, %2};" : "=l"(r) : "f"(lo), "f"(hi)); return r;
}
__device__ __forceinline__ u64 bc2(float x) { return pk2(x, x); }
__device__ __forceinline__ float2 up2(u64 v) {
    float2 f; asm("mov.b64 {%0, %1}, %2;" : "=f"(f.x), "=f"(f.y) : "l"(v)); return f;
}
__device__ __forceinline__ u64 fma2(u64 a, u64 b, u64 c) {
    u64 d; asm("fma.rn.f32x2 %0, %1, %2, %3;" : "=l"(d) : "l"(a), "l"(b), "l"(c)); return d;
}

// ---------------- scratch (device globals; no allocation allowed) ----------
__device__ __align__(16) float d_pool1[N_TOT * 32 * 14 * 14];
__device__ __align__(16) float d_pool2[N_TOT * 3136];
__device__ __align__(16) float d_fc[N_TOT * LATENT];
__device__ __align__(16) float d_rep[N_LAB * LATENT];
__device__ __align__(16) float d_w[LATENT * LATENT];
__device__ __align__(16) float d_w2[32 * 25 * 64];   // conv2 weights [ic][k][oc]
__device__ float d_rhopart[N_LAB];
__device__ float d_rho[1];

__device__ __forceinline__ float sgnf(float x) {
    return (x > 0.f) ? 1.f : ((x < 0.f) ? -1.f : 0.f);
}

// ---------------- one-time conv2 weight transpose: [oc][ic][k] -> [ic][k][oc]
__global__ void transpose_w2_kernel(const float* __restrict__ w) {
    int idx = blockIdx.x * 256 + threadIdx.x;   // 51200 total
    if (idx < 51200) {
        int ic = idx / 1600, rem = idx % 1600;
        int k = rem >> 6, oc = rem & 63;
        d_w2[idx] = w[oc * 800 + ic * 25 + k];
    }
}

// ---------------- conv1 + relu + pool : [N,1,28,28] -> [N,32,14,14] --------
__global__ void conv1_kernel(const float* __restrict__ img, const float* __restrict__ lab,
                             const float* __restrict__ w, const float* __restrict__ b) {
    int n = blockIdx.x;
    const float* src = (n < N_IMG) ? (img + n * 784) : (lab + (n - N_IMG) * 784);
    __shared__ float sin_[32 * 32];
    __shared__ float sw[800];
    __shared__ float sb[32];
    int t = threadIdx.x;
    for (int idx = t; idx < 1024; idx += 256) {
        int y = idx >> 5, x = idx & 31;
        int iy = y - 2, ix = x - 2;
        float v = 0.f;
        if (iy >= 0 && iy < 28 && ix >= 0 && ix < 28) v = src[iy * 28 + ix];
        sin_[idx] = v;
    }
    for (int idx = t; idx < 800; idx += 256) sw[idx] = w[idx];
    if (t < 32) sb[t] = b[t];
    __syncthreads();
    int oc = t >> 3, tp = t & 7;
    float wr[25];
#pragma unroll
    for (int u = 0; u < 25; u++) wr[u] = sw[oc * 25 + u];
    float bias = sb[oc];
    for (int pos = tp; pos < 196; pos += 8) {
        int py = pos / 14, px = pos % 14;
        float win[36];
        int base = (2 * py) * 32 + 2 * px;
#pragma unroll
        for (int wy = 0; wy < 6; wy++)
#pragma unroll
            for (int wx = 0; wx < 6; wx++)
                win[wy * 6 + wx] = sin_[base + wy * 32 + wx];
        u64 pp[6][5];
#pragma unroll
        for (int ky = 0; ky < 6; ky++)
#pragma unroll
            for (int kx = 0; kx < 5; kx++) pp[ky][kx] = pk2(win[ky * 6 + kx], win[ky * 6 + kx + 1]);
        u64 A0 = 0ull, A1 = 0ull;
#pragma unroll
        for (int ky = 0; ky < 5; ky++)
#pragma unroll
            for (int kx = 0; kx < 5; kx++) {
                u64 wp = bc2(wr[ky * 5 + kx]);
                A0 = fma2(wp, pp[ky][kx], A0);
                A1 = fma2(wp, pp[ky + 1][kx], A1);
            }
        float2 f0 = up2(A0), f1 = up2(A1);
        float m = fmaxf(fmaxf(fmaxf(f0.x + bias, 0.f), fmaxf(f0.y + bias, 0.f)),
                        fmaxf(fmaxf(f1.x + bias, 0.f), fmaxf(f1.y + bias, 0.f)));
        d_pool1[n * 6272 + oc * 196 + pos] = m;
    }
}

// ---------------- conv2 + relu + pool : [N,32,14,14] -> [N,64,7,7] ---------
// R10 version (best measured: 537us). 392 thr = 49 pos x 8 oc-groups; weights
// read directly from pre-transposed d_w2[ic][k][oc] as warp-UNIFORM LDG.128
// (one broadcast sector per load); no smem staging, single barrier.
// Per-output accumulation order: ic -> ky -> kx.
__global__ void conv2_kernel(const float* __restrict__ b) {
    int n = blockIdx.x;
    __shared__ float sin_[32 * 18 * 18];  // 10368 floats
    int t = threadIdx.x;                  // 392 threads
    for (int idx = t; idx < 10368; idx += 392) {
        int ic = idx / 324, rem = idx % 324;
        int y = rem / 18, x = rem % 18;
        int iy = y - 2, ix = x - 2;
        float v = 0.f;
        if (iy >= 0 && iy < 14 && ix >= 0 && ix < 14)
            v = d_pool1[n * 6272 + ic * 196 + iy * 14 + ix];
        sin_[idx] = v;
    }
    __syncthreads();                      // the only barrier

    int pos = t % 49, grp = t / 49;       // 49 positions x 8 oc-groups
    int py = pos / 7, px = pos % 7;
    u64 acc[4][4];                        // [oc-pair][subpos 00,01,10,11]
#pragma unroll
    for (int p = 0; p < 4; p++)
#pragma unroll
        for (int q = 0; q < 4; q++) acc[p][q] = 0ull;

    const float* wg = d_w2 + grp * 8;     // [ic][k][oc] slice for this group
    for (int ic = 0; ic < 32; ic++) {
        float win[36];
        int base = ic * 324 + (2 * py) * 18 + 2 * px;   // even -> float2-aligned
#pragma unroll
        for (int wy = 0; wy < 6; wy++) {
            float2 va = *(const float2*)&sin_[base + wy * 18 + 0];
            float2 vb = *(const float2*)&sin_[base + wy * 18 + 2];
            float2 vc = *(const float2*)&sin_[base + wy * 18 + 4];
            win[wy * 6 + 0] = va.x; win[wy * 6 + 1] = va.y;
            win[wy * 6 + 2] = vb.x; win[wy * 6 + 3] = vb.y;
            win[wy * 6 + 4] = vc.x; win[wy * 6 + 5] = vc.y;
        }
        const float* wic = wg + ic * 1600;
#pragma unroll
        for (int ky = 0; ky < 5; ky++)
#pragma unroll
            for (int kx = 0; kx < 5; kx++) {
                const float* swk = wic + (ky * 5 + kx) * 64;   // 16B-aligned
                ulonglong2 wp01 = *(const ulonglong2*)&swk[0];
                ulonglong2 wp23 = *(const ulonglong2*)&swk[4];
                u64 wp0 = wp01.x, wp1 = wp01.y, wp2 = wp23.x, wp3 = wp23.y;
                u64 b00 = bc2(win[ky * 6 + kx]);
                u64 b01 = bc2(win[ky * 6 + kx + 1]);
                u64 b10 = bc2(win[(ky + 1) * 6 + kx]);
                u64 b11 = bc2(win[(ky + 1) * 6 + kx + 1]);
                acc[0][0] = fma2(wp0, b00, acc[0][0]);
                acc[0][1] = fma2(wp0, b01, acc[0][1]);
                acc[0][2] = fma2(wp0, b10, acc[0][2]);
                acc[0][3] = fma2(wp0, b11, acc[0][3]);
                acc[1][0] = fma2(wp1, b00, acc[1][0]);
                acc[1][1] = fma2(wp1, b01, acc[1][1]);
                acc[1][2] = fma2(wp1, b10, acc[1][2]);
                acc[1][3] = fma2(wp1, b11, acc[1][3]);
                acc[2][0] = fma2(wp2, b00, acc[2][0]);
                acc[2][1] = fma2(wp2, b01, acc[2][1]);
                acc[2][2] = fma2(wp2, b10, acc[2][2]);
                acc[2][3] = fma2(wp2, b11, acc[2][3]);
                acc[3][0] = fma2(wp3, b00, acc[3][0]);
                acc[3][1] = fma2(wp3, b01, acc[3][1]);
                acc[3][2] = fma2(wp3, b10, acc[3][2]);
                acc[3][3] = fma2(wp3, b11, acc[3][3]);
            }
    }
#pragma unroll
    for (int p = 0; p < 4; p++) {
        int oc0 = grp * 8 + 2 * p;
        float bias0 = b[oc0], bias1 = b[oc0 + 1];
        float2 v0 = up2(acc[p][0]), v1 = up2(acc[p][1]);
        float2 v2 = up2(acc[p][2]), v3 = up2(acc[p][3]);
        float m0 = fmaxf(fmaxf(fmaxf(v0.x + bias0, 0.f), fmaxf(v1.x + bias0, 0.f)),
                         fmaxf(fmaxf(v2.x + bias0, 0.f), fmaxf(v3.x + bias0, 0.f)));
        float m1 = fmaxf(fmaxf(fmaxf(v0.y + bias1, 0.f), fmaxf(v1.y + bias1, 0.f)),
                         fmaxf(fmaxf(v2.y + bias1, 0.f), fmaxf(v3.y + bias1, 0.f)));
        d_pool2[n * 3136 + oc0 * 49 + pos] = m0;
        d_pool2[n * 3136 + (oc0 + 1) * 49 + pos] = m1;
    }
}

// ---------------- fc1: [1152,3136] @ [512,3136]^T + b -> d_fc --------------
__global__ void fc1_kernel(const float* __restrict__ fw, const float* __restrict__ fb) {
    __shared__ float As[32][66];
    __shared__ float Bs[32][66];
    int t = threadIdx.x;
    int tx = t & 15, ty = t >> 4;
    int m0 = blockIdx.x * 64;
    int n0 = blockIdx.y * 64;
    u64 acc[4][2];
#pragma unroll
    for (int i = 0; i < 4; i++) { acc[i][0] = 0ull; acc[i][1] = 0ull; }

    for (int k0 = 0; k0 < 3136; k0 += 32) {
        __syncthreads();
        for (int id = t; id < 512; id += 256) {
            int row = id >> 3, kk4 = id & 7;
            float4 v = *(const float4*)&d_pool2[(m0 + row) * 3136 + k0 + kk4 * 4];
            As[kk4 * 4 + 0][row] = v.x;
            As[kk4 * 4 + 1][row] = v.y;
            As[kk4 * 4 + 2][row] = v.z;
            As[kk4 * 4 + 3][row] = v.w;
        }
        for (int id = t; id < 512; id += 256) {
            int row = id >> 3, kk4 = id & 7;
            float4 v = *(const float4*)&fw[(n0 + row) * 3136 + k0 + kk4 * 4];
            Bs[kk4 * 4 + 0][row] = v.x;
            Bs[kk4 * 4 + 1][row] = v.y;
            Bs[kk4 * 4 + 2][row] = v.z;
            Bs[kk4 * 4 + 3][row] = v.w;
        }
        __syncthreads();
#pragma unroll
        for (int kk = 0; kk < 32; kk++) {
            u64 b01 = *(const u64*)&Bs[kk][tx * 4];
            u64 b23 = *(const u64*)&Bs[kk][tx * 4 + 2];
#pragma unroll
            for (int i = 0; i < 4; i++) {
                u64 ap = bc2(As[kk][ty * 4 + i]);
                acc[i][0] = fma2(ap, b01, acc[i][0]);
                acc[i][1] = fma2(ap, b23, acc[i][1]);
            }
        }
    }
#pragma unroll
    for (int i = 0; i < 4; i++) {
        int m = m0 + ty * 4 + i;
        float2 c01 = up2(acc[i][0]), c23 = up2(acc[i][1]);
        int nn = n0 + tx * 4;
        d_fc[m * 512 + nn + 0] = c01.x + fb[nn + 0];
        d_fc[m * 512 + nn + 1] = c01.y + fb[nn + 1];
        d_fc[m * 512 + nn + 2] = c23.x + fb[nn + 2];
        d_fc[m * 512 + nn + 3] = c23.y + fb[nn + 3];
    }
}

// ---------------- rep = tanh(fc rows 1024..1151) + rho partial sums --------
__global__ void tanh_rep_kernel() {
    int bb = blockIdx.x;
    int t = threadIdx.x;
    float v = tanhf(d_fc[(N_IMG + bb) * LATENT + t]);
    d_rep[bb * LATENT + t] = v;
    float s = v;
#pragma unroll
    for (int off = 16; off > 0; off >>= 1) s += __shfl_down_sync(0xffffffffu, s, off);
    __shared__ float ws[16];
    if ((t & 31) == 0) ws[t >> 5] = s;
    __syncthreads();
    if (t == 0) {
        float tot = 0.f;
        for (int i = 0; i < 16; i++) tot += ws[i];
        d_rhopart[bb] = tot;
    }
}

__global__ void rho_kernel() {
    if (threadIdx.x == 0) {
        float s = 0.f;
        for (int i = 0; i < 128; i++) s += d_rhopart[i];
        d_rho[0] = s / 65536.0f;
    }
}

// ---------------- Hopfield W = ((rep-rho)^T (rep-rho)) * (1-I) / 128 -------
__global__ void hopw_kernel() {
    __shared__ float ti[128][32];
    __shared__ float tj[128][32];
    float rho = d_rho[0];
    int i0 = blockIdx.x * 32, j0 = blockIdx.y * 32;
    int t = threadIdx.x;
    for (int idx = t; idx < 4096; idx += 256) {
        int bb = idx >> 5, c = idx & 31;
        ti[bb][c] = d_rep[bb * 512 + i0 + c] - rho;
        tj[bb][c] = d_rep[bb * 512 + j0 + c] - rho;
    }
    __syncthreads();
    int tx = t & 15, ty = t >> 4;
    float a00 = 0.f, a01 = 0.f, a10 = 0.f, a11 = 0.f;
    for (int bb = 0; bb < 128; bb++) {
        float x0 = ti[bb][tx * 2], x1 = ti[bb][tx * 2 + 1];
        float y0 = tj[bb][ty * 2], y1 = tj[bb][ty * 2 + 1];
        a00 = fmaf(x0, y0, a00); a01 = fmaf(x0, y1, a01);
        a10 = fmaf(x1, y0, a10); a11 = fmaf(x1, y1, a11);
    }
    const float inv = 1.f / 128.f;
    int i = i0 + tx * 2, j = j0 + ty * 2;
    d_w[i * 512 + j]             = (i == j)         ? 0.f : a00 * inv;
    d_w[i * 512 + (j + 1)]       = (i == j + 1)     ? 0.f : a01 * inv;
    d_w[(i + 1) * 512 + j]       = (i + 1 == j)     ? 0.f : a10 * inv;
    d_w[(i + 1) * 512 + (j + 1)] = (i + 1 == j + 1) ? 0.f : a11 * inv;
}

// ---------------- label = softmax(lat @ fcn_w^T + fcn_b) -------------------
__global__ void label_kernel(const float* __restrict__ fw, const float* __restrict__ fb,
                             float* __restrict__ out) {
    int blk = blockIdx.x;          // images blk*4 .. blk*4+3
    int l = threadIdx.x;           // 0..127
    int lane = l & 31, warp = l >> 5;
    __shared__ float slat[4][512];
    __shared__ float redm[4], reds[4];
    for (int idx = l; idx < 512; idx += 128) {
        int img = idx >> 7, k4 = idx & 127;
        ((float4*)&slat[img][0])[k4] = ((const float4*)(d_fc + (blk * 4 + img) * 512))[k4];
    }
    __syncthreads();
    float acc[4];
    float bias = fb[l];
#pragma unroll
    for (int img = 0; img < 4; img++) acc[img] = bias;
    const float4* fr = (const float4*)(fw + l * 512);
    for (int kc = 0; kc < 16; kc++) {
        float4 wv[8];
#pragma unroll
        for (int c = 0; c < 8; c++) wv[c] = fr[kc * 8 + c];
#pragma unroll
        for (int img = 0; img < 4; img++) {
            const float4* s4 = (const float4*)&slat[img][kc * 32];
#pragma unroll
            for (int c = 0; c < 8; c++) {
                float4 sv = s4[c];
                acc[img] = fmaf(sv.x, wv[c].x, acc[img]);
                acc[img] = fmaf(sv.y, wv[c].y, acc[img]);
                acc[img] = fmaf(sv.z, wv[c].z, acc[img]);
                acc[img] = fmaf(sv.w, wv[c].w, acc[img]);
            }
        }
    }
    for (int img = 0; img < 4; img++) {
        float m = acc[img];
#pragma unroll
        for (int off = 16; off > 0; off >>= 1)
            m = fmaxf(m, __shfl_xor_sync(0xffffffffu, m, off));
        if (lane == 0) redm[warp] = m;
        __syncthreads();
        m = fmaxf(fmaxf(redm[0], redm[1]), fmaxf(redm[2], redm[3]));
        float ex = expf(acc[img] - m);
        float s = ex;
#pragma unroll
        for (int off = 16; off > 0; off >>= 1)
            s += __shfl_xor_sync(0xffffffffu, s, off);
        if (lane == 0) reds[warp] = s;
        __syncthreads();
        s = reds[0] + reds[1] + reds[2] + reds[3];
        out[131072 + (blk * 4 + img) * 128 + l] = ex / s;
        __syncthreads();
    }
}

// ---------------- Hopfield clustering (sparse union-delta) + softmax -------
__global__ void __launch_bounds__(512, 1) cluster_kernel(float* __restrict__ out) {
    __shared__ float coef[512][8];
    __shared__ int   ulist[512];
    __shared__ int   warpcnt[16], warpbase[16];
    __shared__ int   s_nf, doneflag;
    __shared__ float epart[16][8];
    __shared__ float esm[8];
    __shared__ unsigned wA[16], wB[16];
    __shared__ float dots[8][128];

    int t = threadIdx.x;
    int lane = t & 31, warp = t >> 5;
    int row0 = blockIdx.x * 8;
    const float* wc = d_w + t;

    float h[8], sp[8], sp2[8], mins[8], min_e[8];
    const float nanv = __int_as_float(0x7fffffff);

#pragma unroll
    for (int r = 0; r < 8; r++) {
        float v = tanhf(d_fc[(row0 + r) * 512 + t]);
        sp[r] = v;
        sp2[r] = nanv;
        mins[r] = 0.f;
        min_e[r] = INFINITY;
    }
    *(float4*)&coef[t][0] = make_float4(sp[0], sp[1], sp[2], sp[3]);
    *(float4*)&coef[t][4] = make_float4(sp[4], sp[5], sp[6], sp[7]);
    __syncthreads();

    // prologue full GEMV: h = s0 @ w
    {
        u64 hh[4] = {0ull, 0ull, 0ull, 0ull};
#pragma unroll 4
        for (int j = 0; j < 512; j++) {
            u64 wp = bc2(wc[j * 512]);
            ulonglong2 cA = *(const ulonglong2*)&coef[j][0];
            ulonglong2 cB = *(const ulonglong2*)&coef[j][4];
            hh[0] = fma2(wp, cA.x, hh[0]);
            hh[1] = fma2(wp, cA.y, hh[1]);
            hh[2] = fma2(wp, cB.x, hh[2]);
            hh[3] = fma2(wp, cB.y, hh[3]);
        }
#pragma unroll
        for (int q = 0; q < 4; q++) {
            float2 f = up2(hh[q]);
            h[2 * q] = f.x; h[2 * q + 1] = f.y;
        }
    }

    for (int iter = 0; iter < LATENT; iter++) {
        float sn[8], cf[8];
        unsigned a = 0, b = 0;
        bool flip = false;
#pragma unroll
        for (int r = 0; r < 8; r++) {
            float v = fabsf(sp[r]) * sgnf(h[r]);
            sn[r] = v;
            cf[r] = v - sp[r];
            if (cf[r] != 0.f) flip = true;
            if (v == sp[r]) a |= (1u << r);
            if (v == sp2[r]) b |= (1u << r);
        }
        a = __reduce_and_sync(0xffffffffu, a);
        b = __reduce_and_sync(0xffffffffu, b);
        unsigned bal = __ballot_sync(0xffffffffu, flip);
        if (lane == 0) { wA[warp] = a; wB[warp] = b; warpcnt[warp] = __popc(bal); }
        __syncthreads();   // S1
        *(float4*)&coef[t][0] = make_float4(cf[0], cf[1], cf[2], cf[3]);
        *(float4*)&coef[t][4] = make_float4(cf[4], cf[5], cf[6], cf[7]);
        if (t == 0) {
            int accn = 0;
            unsigned A = 0xffu, B = 0xffu;
            for (int q = 0; q < 16; q++) {
                warpbase[q] = accn;
                accn += warpcnt[q];
                A &= wA[q]; B &= wB[q];
            }
            s_nf = accn;
            doneflag = ((A | B) == 0xffu) ? 1 : 0;
        }
        __syncthreads();   // S2
        if (flip) {
            int rank = __popc(bal & ((1u << lane) - 1u));
            ulist[warpbase[warp] + rank] = t;
        }
        __syncthreads();   // S3
        int nf = s_nf;
        int done = doneflag;

        // delta update: h += coef[j] * w[j][t] over union list
        {
            u64 hh[4];
#pragma unroll
            for (int q = 0; q < 4; q++) hh[q] = pk2(h[2 * q], h[2 * q + 1]);
            int i = 0;
            for (; i + 4 <= nf; i += 4) {
                int j0 = ulist[i], j1 = ulist[i + 1], j2 = ulist[i + 2], j3 = ulist[i + 3];
                float w0 = wc[j0 * 512], w1 = wc[j1 * 512];
                float w2 = wc[j2 * 512], w3 = wc[j3 * 512];
                {
                    u64 wp = bc2(w0);
                    ulonglong2 cA = *(const ulonglong2*)&coef[j0][0];
                    ulonglong2 cB = *(const ulonglong2*)&coef[j0][4];
                    hh[0] = fma2(wp, cA.x, hh[0]); hh[1] = fma2(wp, cA.y, hh[1]);
                    hh[2] = fma2(wp, cB.x, hh[2]); hh[3] = fma2(wp, cB.y, hh[3]);
                }
                {
                    u64 wp = bc2(w1);
                    ulonglong2 cA = *(const ulonglong2*)&coef[j1][0];
                    ulonglong2 cB = *(const ulonglong2*)&coef[j1][4];
                    hh[0] = fma2(wp, cA.x, hh[0]); hh[1] = fma2(wp, cA.y, hh[1]);
                    hh[2] = fma2(wp, cB.x, hh[2]); hh[3] = fma2(wp, cB.y, hh[3]);
                }
                {
                    u64 wp = bc2(w2);
                    ulonglong2 cA = *(const ulonglong2*)&coef[j2][0];
                    ulonglong2 cB = *(const ulonglong2*)&coef[j2][4];
                    hh[0] = fma2(wp, cA.x, hh[0]); hh[1] = fma2(wp, cA.y, hh[1]);
                    hh[2] = fma2(wp, cB.x, hh[2]); hh[3] = fma2(wp, cB.y, hh[3]);
                }
                {
                    u64 wp = bc2(w3);
                    ulonglong2 cA = *(const ulonglong2*)&coef[j3][0];
                    ulonglong2 cB = *(const ulonglong2*)&coef[j3][4];
                    hh[0] = fma2(wp, cA.x, hh[0]); hh[1] = fma2(wp, cA.y, hh[1]);
                    hh[2] = fma2(wp, cB.x, hh[2]); hh[3] = fma2(wp, cB.y, hh[3]);
                }
            }
            for (; i < nf; i++) {
                int j = ulist[i];
                u64 wp = bc2(wc[j * 512]);
                ulonglong2 cA = *(const ulonglong2*)&coef[j][0];
                ulonglong2 cB = *(const ulonglong2*)&coef[j][4];
                hh[0] = fma2(wp, cA.x, hh[0]); hh[1] = fma2(wp, cA.y, hh[1]);
                hh[2] = fma2(wp, cB.x, hh[2]); hh[3] = fma2(wp, cB.y, hh[3]);
            }
#pragma unroll
            for (int q = 0; q < 4; q++) {
                float2 f = up2(hh[q]);
                h[2 * q] = f.x; h[2 * q + 1] = f.y;
            }
        }

        // energy e[r] = -sum_t sn[r]*h[r]
        float p[8];
#pragma unroll
        for (int r = 0; r < 8; r++) p[r] = sn[r] * h[r];
#pragma unroll
        for (int r = 0; r < 8; r++) {
#pragma unroll
            for (int off = 16; off > 0; off >>= 1)
                p[r] += __shfl_down_sync(0xffffffffu, p[r], off);
        }
        if (lane == 0) {
#pragma unroll
            for (int r = 0; r < 8; r++) epart[warp][r] = p[r];
        }
        __syncthreads();   // S4
        if (t < 8) {
            float e = 0.f;
            for (int q = 0; q < 16; q++) e += epart[q][t];
            esm[t] = -e;
        }
        __syncthreads();   // S5
#pragma unroll
        for (int r = 0; r < 8; r++) {
            float e = esm[r];
            if (e < min_e[r]) { min_e[r] = e; mins[r] = sn[r]; }
            sp2[r] = sp[r]; sp[r] = sn[r];
        }
        if (done) break;
    }

    // ---------------- epilogue: out = softmax(|min_s @ rep^T|) -------------
    __syncthreads();
    *(float4*)&coef[t][0] = make_float4(mins[0], mins[1], mins[2], mins[3]);
    *(float4*)&coef[t][4] = make_float4(mins[4], mins[5], mins[6], mins[7]);
    __syncthreads();

    int l = t >> 2, q = t & 3;
#pragma unroll
    for (int r = 0; r < 8; r++) {
        const float4* rp = (const float4*)(d_rep + l * 512 + q * 128);
        float v = 0.f;
#pragma unroll 8
        for (int i4 = 0; i4 < 32; i4++) {
            float4 rv = rp[i4];
            int j = q * 128 + i4 * 4;
            v = fmaf(coef[j + 0][r], rv.x, v);
            v = fmaf(coef[j + 1][r], rv.y, v);
            v = fmaf(coef[j + 2][r], rv.z, v);
            v = fmaf(coef[j + 3][r], rv.w, v);
        }
        v += __shfl_xor_sync(0xffffffffu, v, 1);
        v += __shfl_xor_sync(0xffffffffu, v, 2);
        if (q == 0) dots[r][l] = fabsf(v);
    }
    __syncthreads();

    if (warp < 8) {
        int r = warp;
        float v0 = dots[r][lane], v1 = dots[r][lane + 32];
        float v2 = dots[r][lane + 64], v3 = dots[r][lane + 96];
        float m = fmaxf(fmaxf(v0, v1), fmaxf(v2, v3));
#pragma unroll
        for (int off = 16; off > 0; off >>= 1)
            m = fmaxf(m, __shfl_xor_sync(0xffffffffu, m, off));
        float e0 = expf(v0 - m), e1 = expf(v1 - m), e2 = expf(v2 - m), e3 = expf(v3 - m);
        float s = e0 + e1 + e2 + e3;
#pragma unroll
        for (int off = 16; off > 0; off >>= 1)
            s += __shfl_xor_sync(0xffffffffu, s, off);
        float inv = 1.f / s;
        float* o = out + (row0 + r) * 128;
        o[lane] = e0 * inv;
        o[lane + 32] = e1 * inv;
        o[lane + 64] = e2 * inv;
        o[lane + 96] = e3 * inv;
    }
}

// ---------------------------------------------------------------------------
extern "C" void kernel_launch(void* const* d_in, const int* in_sizes, int n_in,
                              void* d_out, int out_size) {
    const float* image     = (const float*)d_in[0];
    const float* label_img = (const float*)d_in[1];
    const float* c1w       = (const float*)d_in[2];
    const float* c1b       = (const float*)d_in[3];
    const float* c2w       = (const float*)d_in[4];
    const float* c2b       = (const float*)d_in[5];
    const float* f1w       = (const float*)d_in[6];
    const float* f1b       = (const float*)d_in[7];
    const float* fnw       = (const float*)d_in[8];
    const float* fnb       = (const float*)d_in[9];
    float* out = (float*)d_out;

    // launch index 3 is the ncu-profiled slot -> fc1 this round
    transpose_w2_kernel<<<200, 256>>>(c2w);               // 0
    conv1_kernel<<<N_TOT, 256>>>(image, label_img, c1w, c1b); // 1
    conv2_kernel<<<N_TOT, 392>>>(c2b);                    // 2
    fc1_kernel<<<dim3(18, 8), 256>>>(f1w, f1b);           // 3  <- profiled
    label_kernel<<<256, 128>>>(fnw, fnb, out);
    tanh_rep_kernel<<<128, 512>>>();
    rho_kernel<<<1, 32>>>();
    hopw_kernel<<<dim3(16, 16), 256>>>();
    cluster_kernel<<<128, 512>>>(out);
}

// round 13
// speedup vs baseline: 1.1664x; 1.0533x over previous
#include <cuda_runtime.h>
#include <math.h>

#define N_IMG 1024
#define N_LAB 128
#define N_TOT 1152
#define LATENT 512
#define NLABEL 128

typedef unsigned long long u64;

// ---- packed f32x2 helpers (lanewise rn-FMA; bitwise == two scalar fmaf) ----
__device__ __forceinline__ u64 pk2(float lo, float hi) {
    u64 r; asm("mov.b64 %0, {%1, %2};" : "=l"(r) : "f"(lo), "f"(hi)); return r;
}
__device__ __forceinline__ u64 bc2(float x) { return pk2(x, x); }
__device__ __forceinline__ float2 up2(u64 v) {
    float2 f; asm("mov.b64 {%0, %1}, %2;" : "=f"(f.x), "=f"(f.y) : "l"(v)); return f;
}
__device__ __forceinline__ u64 fma2(u64 a, u64 b, u64 c) {
    u64 d; asm("fma.rn.f32x2 %0, %1, %2, %3;" : "=l"(d) : "l"(a), "l"(b), "l"(c)); return d;
}

// ---------------- scratch (device globals; no allocation allowed) ----------
__device__ __align__(16) float d_pool1[N_TOT * 32 * 14 * 14];
__device__ __align__(16) float d_pool2[N_TOT * 3136];
__device__ __align__(16) float d_fc[N_TOT * LATENT];
__device__ __align__(16) float d_rep[N_LAB * LATENT];
__device__ __align__(16) float d_w[LATENT * LATENT];
__device__ __align__(16) float d_w2[32 * 25 * 64];   // conv2 weights [ic][k][oc]
__device__ float d_rhopart[N_LAB];
__device__ float d_rho[1];

__device__ __forceinline__ float sgnf(float x) {
    return (x > 0.f) ? 1.f : ((x < 0.f) ? -1.f : 0.f);
}

// ---------------- one-time conv2 weight transpose: [oc][ic][k] -> [ic][k][oc]
__global__ void transpose_w2_kernel(const float* __restrict__ w) {
    int idx = blockIdx.x * 256 + threadIdx.x;   // 51200 total
    if (idx < 51200) {
        int ic = idx / 1600, rem = idx % 1600;
        int k = rem >> 6, oc = rem & 63;
        d_w2[idx] = w[oc * 800 + ic * 25 + k];
    }
}

// ---------------- conv1 + relu + pool : [N,1,28,28] -> [N,32,14,14] --------
__global__ void conv1_kernel(const float* __restrict__ img, const float* __restrict__ lab,
                             const float* __restrict__ w, const float* __restrict__ b) {
    int n = blockIdx.x;
    const float* src = (n < N_IMG) ? (img + n * 784) : (lab + (n - N_IMG) * 784);
    __shared__ float sin_[32 * 32];
    __shared__ float sw[800];
    __shared__ float sb[32];
    int t = threadIdx.x;
    for (int idx = t; idx < 1024; idx += 256) {
        int y = idx >> 5, x = idx & 31;
        int iy = y - 2, ix = x - 2;
        float v = 0.f;
        if (iy >= 0 && iy < 28 && ix >= 0 && ix < 28) v = src[iy * 28 + ix];
        sin_[idx] = v;
    }
    for (int idx = t; idx < 800; idx += 256) sw[idx] = w[idx];
    if (t < 32) sb[t] = b[t];
    __syncthreads();
    int oc = t >> 3, tp = t & 7;
    float wr[25];
#pragma unroll
    for (int u = 0; u < 25; u++) wr[u] = sw[oc * 25 + u];
    float bias = sb[oc];
    for (int pos = tp; pos < 196; pos += 8) {
        int py = pos / 14, px = pos % 14;
        float win[36];
        int base = (2 * py) * 32 + 2 * px;
#pragma unroll
        for (int wy = 0; wy < 6; wy++)
#pragma unroll
            for (int wx = 0; wx < 6; wx++)
                win[wy * 6 + wx] = sin_[base + wy * 32 + wx];
        u64 pp[6][5];
#pragma unroll
        for (int ky = 0; ky < 6; ky++)
#pragma unroll
            for (int kx = 0; kx < 5; kx++) pp[ky][kx] = pk2(win[ky * 6 + kx], win[ky * 6 + kx + 1]);
        u64 A0 = 0ull, A1 = 0ull;
#pragma unroll
        for (int ky = 0; ky < 5; ky++)
#pragma unroll
            for (int kx = 0; kx < 5; kx++) {
                u64 wp = bc2(wr[ky * 5 + kx]);
                A0 = fma2(wp, pp[ky][kx], A0);
                A1 = fma2(wp, pp[ky + 1][kx], A1);
            }
        float2 f0 = up2(A0), f1 = up2(A1);
        float m = fmaxf(fmaxf(fmaxf(f0.x + bias, 0.f), fmaxf(f0.y + bias, 0.f)),
                        fmaxf(fmaxf(f1.x + bias, 0.f), fmaxf(f1.y + bias, 0.f)));
        d_pool1[n * 6272 + oc * 196 + pos] = m;
    }
}

// ---------------- conv2 + relu + pool : [N,32,14,14] -> [N,64,7,7] ---------
// R10 version (best measured: 537us). 392 thr = 49 pos x 8 oc-groups; weights
// read directly from pre-transposed d_w2[ic][k][oc] as warp-UNIFORM LDG.128.
__global__ void conv2_kernel(const float* __restrict__ b) {
    int n = blockIdx.x;
    __shared__ float sin_[32 * 18 * 18];  // 10368 floats
    int t = threadIdx.x;                  // 392 threads
    for (int idx = t; idx < 10368; idx += 392) {
        int ic = idx / 324, rem = idx % 324;
        int y = rem / 18, x = rem % 18;
        int iy = y - 2, ix = x - 2;
        float v = 0.f;
        if (iy >= 0 && iy < 14 && ix >= 0 && ix < 14)
            v = d_pool1[n * 6272 + ic * 196 + iy * 14 + ix];
        sin_[idx] = v;
    }
    __syncthreads();                      // the only barrier

    int pos = t % 49, grp = t / 49;       // 49 positions x 8 oc-groups
    int py = pos / 7, px = pos % 7;
    u64 acc[4][4];                        // [oc-pair][subpos 00,01,10,11]
#pragma unroll
    for (int p = 0; p < 4; p++)
#pragma unroll
        for (int q = 0; q < 4; q++) acc[p][q] = 0ull;

    const float* wg = d_w2 + grp * 8;     // [ic][k][oc] slice for this group
    for (int ic = 0; ic < 32; ic++) {
        float win[36];
        int base = ic * 324 + (2 * py) * 18 + 2 * px;   // even -> float2-aligned
#pragma unroll
        for (int wy = 0; wy < 6; wy++) {
            float2 va = *(const float2*)&sin_[base + wy * 18 + 0];
            float2 vb = *(const float2*)&sin_[base + wy * 18 + 2];
            float2 vc = *(const float2*)&sin_[base + wy * 18 + 4];
            win[wy * 6 + 0] = va.x; win[wy * 6 + 1] = va.y;
            win[wy * 6 + 2] = vb.x; win[wy * 6 + 3] = vb.y;
            win[wy * 6 + 4] = vc.x; win[wy * 6 + 5] = vc.y;
        }
        const float* wic = wg + ic * 1600;
#pragma unroll
        for (int ky = 0; ky < 5; ky++)
#pragma unroll
            for (int kx = 0; kx < 5; kx++) {
                const float* swk = wic + (ky * 5 + kx) * 64;   // 16B-aligned
                ulonglong2 wp01 = *(const ulonglong2*)&swk[0];
                ulonglong2 wp23 = *(const ulonglong2*)&swk[4];
                u64 wp0 = wp01.x, wp1 = wp01.y, wp2 = wp23.x, wp3 = wp23.y;
                u64 b00 = bc2(win[ky * 6 + kx]);
                u64 b01 = bc2(win[ky * 6 + kx + 1]);
                u64 b10 = bc2(win[(ky + 1) * 6 + kx]);
                u64 b11 = bc2(win[(ky + 1) * 6 + kx + 1]);
                acc[0][0] = fma2(wp0, b00, acc[0][0]);
                acc[0][1] = fma2(wp0, b01, acc[0][1]);
                acc[0][2] = fma2(wp0, b10, acc[0][2]);
                acc[0][3] = fma2(wp0, b11, acc[0][3]);
                acc[1][0] = fma2(wp1, b00, acc[1][0]);
                acc[1][1] = fma2(wp1, b01, acc[1][1]);
                acc[1][2] = fma2(wp1, b10, acc[1][2]);
                acc[1][3] = fma2(wp1, b11, acc[1][3]);
                acc[2][0] = fma2(wp2, b00, acc[2][0]);
                acc[2][1] = fma2(wp2, b01, acc[2][1]);
                acc[2][2] = fma2(wp2, b10, acc[2][2]);
                acc[2][3] = fma2(wp2, b11, acc[2][3]);
                acc[3][0] = fma2(wp3, b00, acc[3][0]);
                acc[3][1] = fma2(wp3, b01, acc[3][1]);
                acc[3][2] = fma2(wp3, b10, acc[3][2]);
                acc[3][3] = fma2(wp3, b11, acc[3][3]);
            }
    }
#pragma unroll
    for (int p = 0; p < 4; p++) {
        int oc0 = grp * 8 + 2 * p;
        float bias0 = b[oc0], bias1 = b[oc0 + 1];
        float2 v0 = up2(acc[p][0]), v1 = up2(acc[p][1]);
        float2 v2 = up2(acc[p][2]), v3 = up2(acc[p][3]);
        float m0 = fmaxf(fmaxf(fmaxf(v0.x + bias0, 0.f), fmaxf(v1.x + bias0, 0.f)),
                         fmaxf(fmaxf(v2.x + bias0, 0.f), fmaxf(v3.x + bias0, 0.f)));
        float m1 = fmaxf(fmaxf(fmaxf(v0.y + bias1, 0.f), fmaxf(v1.y + bias1, 0.f)),
                         fmaxf(fmaxf(v2.y + bias1, 0.f), fmaxf(v3.y + bias1, 0.f)));
        d_pool2[n * 3136 + oc0 * 49 + pos] = m0;
        d_pool2[n * 3136 + (oc0 + 1) * 49 + pos] = m1;
    }
}

// ---------------- fc1: [1152,3136] @ [512,3136]^T + b -> d_fc --------------
// v2: M-tile 32 (grid 288 = ~2 CTAs/SM) + double-buffered smem (1 barrier/iter,
// LDG of next tile overlaps compute). Per-output accumulation order unchanged
// (k ascending, cols paired (0,1)/(2,3)).
__global__ void __launch_bounds__(256, 1) fc1_kernel(const float* __restrict__ fw,
                                                     const float* __restrict__ fb) {
    __shared__ float As[2][32][34];   // [buf][k][m]
    __shared__ float Bs[2][32][66];   // [buf][k][n]
    int t = threadIdx.x;
    int tx = t & 15, ty = t >> 4;
    int m0 = blockIdx.x * 32;
    int n0 = blockIdx.y * 64;

    int arow = t >> 3, ak4 = t & 7;   // As loader: 32 rows x 8 float4

    u64 acc[2][2];
#pragma unroll
    for (int i = 0; i < 2; i++) { acc[i][0] = 0ull; acc[i][1] = 0ull; }

    // ---- load tile kt=0 into buf 0
    {
        float4 va = *(const float4*)&d_pool2[(m0 + arow) * 3136 + ak4 * 4];
        As[0][ak4 * 4 + 0][arow] = va.x;
        As[0][ak4 * 4 + 1][arow] = va.y;
        As[0][ak4 * 4 + 2][arow] = va.z;
        As[0][ak4 * 4 + 3][arow] = va.w;
#pragma unroll
        for (int u = 0; u < 2; u++) {
            int id = t + u * 256;
            int row = id >> 3, k4 = id & 7;
            float4 vb = *(const float4*)&fw[(n0 + row) * 3136 + k4 * 4];
            Bs[0][k4 * 4 + 0][row] = vb.x;
            Bs[0][k4 * 4 + 1][row] = vb.y;
            Bs[0][k4 * 4 + 2][row] = vb.z;
            Bs[0][k4 * 4 + 3][row] = vb.w;
        }
    }
    __syncthreads();

    for (int kt = 0; kt < 98; kt++) {
        int cur = kt & 1;
        if (kt < 97) {                 // prefetch next tile into the other buf
            int nxt = cur ^ 1;
            int k0 = (kt + 1) * 32;
            float4 va = *(const float4*)&d_pool2[(m0 + arow) * 3136 + k0 + ak4 * 4];
            As[nxt][ak4 * 4 + 0][arow] = va.x;
            As[nxt][ak4 * 4 + 1][arow] = va.y;
            As[nxt][ak4 * 4 + 2][arow] = va.z;
            As[nxt][ak4 * 4 + 3][arow] = va.w;
#pragma unroll
            for (int u = 0; u < 2; u++) {
                int id = t + u * 256;
                int row = id >> 3, k4 = id & 7;
                float4 vb = *(const float4*)&fw[(n0 + row) * 3136 + k0 + k4 * 4];
                Bs[nxt][k4 * 4 + 0][row] = vb.x;
                Bs[nxt][k4 * 4 + 1][row] = vb.y;
                Bs[nxt][k4 * 4 + 2][row] = vb.z;
                Bs[nxt][k4 * 4 + 3][row] = vb.w;
            }
        }
#pragma unroll
        for (int kk = 0; kk < 32; kk++) {
            u64 b01 = *(const u64*)&Bs[cur][kk][tx * 4];
            u64 b23 = *(const u64*)&Bs[cur][kk][tx * 4 + 2];
#pragma unroll
            for (int i = 0; i < 2; i++) {
                u64 ap = bc2(As[cur][kk][ty * 2 + i]);
                acc[i][0] = fma2(ap, b01, acc[i][0]);
                acc[i][1] = fma2(ap, b23, acc[i][1]);
            }
        }
        __syncthreads();               // next buf filled AND cur free for reuse
    }
#pragma unroll
    for (int i = 0; i < 2; i++) {
        int m = m0 + ty * 2 + i;
        float2 c01 = up2(acc[i][0]), c23 = up2(acc[i][1]);
        int nn = n0 + tx * 4;
        d_fc[m * 512 + nn + 0] = c01.x + fb[nn + 0];
        d_fc[m * 512 + nn + 1] = c01.y + fb[nn + 1];
        d_fc[m * 512 + nn + 2] = c23.x + fb[nn + 2];
        d_fc[m * 512 + nn + 3] = c23.y + fb[nn + 3];
    }
}

// ---------------- rep = tanh(fc rows 1024..1151) + rho partial sums --------
__global__ void tanh_rep_kernel() {
    int bb = blockIdx.x;
    int t = threadIdx.x;
    float v = tanhf(d_fc[(N_IMG + bb) * LATENT + t]);
    d_rep[bb * LATENT + t] = v;
    float s = v;
#pragma unroll
    for (int off = 16; off > 0; off >>= 1) s += __shfl_down_sync(0xffffffffu, s, off);
    __shared__ float ws[16];
    if ((t & 31) == 0) ws[t >> 5] = s;
    __syncthreads();
    if (t == 0) {
        float tot = 0.f;
        for (int i = 0; i < 16; i++) tot += ws[i];
        d_rhopart[bb] = tot;
    }
}

__global__ void rho_kernel() {
    if (threadIdx.x == 0) {
        float s = 0.f;
        for (int i = 0; i < 128; i++) s += d_rhopart[i];
        d_rho[0] = s / 65536.0f;
    }
}

// ---------------- Hopfield W = ((rep-rho)^T (rep-rho)) * (1-I) / 128 -------
__global__ void hopw_kernel() {
    __shared__ float ti[128][32];
    __shared__ float tj[128][32];
    float rho = d_rho[0];
    int i0 = blockIdx.x * 32, j0 = blockIdx.y * 32;
    int t = threadIdx.x;
    for (int idx = t; idx < 4096; idx += 256) {
        int bb = idx >> 5, c = idx & 31;
        ti[bb][c] = d_rep[bb * 512 + i0 + c] - rho;
        tj[bb][c] = d_rep[bb * 512 + j0 + c] - rho;
    }
    __syncthreads();
    int tx = t & 15, ty = t >> 4;
    float a00 = 0.f, a01 = 0.f, a10 = 0.f, a11 = 0.f;
    for (int bb = 0; bb < 128; bb++) {
        float x0 = ti[bb][tx * 2], x1 = ti[bb][tx * 2 + 1];
        float y0 = tj[bb][ty * 2], y1 = tj[bb][ty * 2 + 1];
        a00 = fmaf(x0, y0, a00); a01 = fmaf(x0, y1, a01);
        a10 = fmaf(x1, y0, a10); a11 = fmaf(x1, y1, a11);
    }
    const float inv = 1.f / 128.f;
    int i = i0 + tx * 2, j = j0 + ty * 2;
    d_w[i * 512 + j]             = (i == j)         ? 0.f : a00 * inv;
    d_w[i * 512 + (j + 1)]       = (i == j + 1)     ? 0.f : a01 * inv;
    d_w[(i + 1) * 512 + j]       = (i + 1 == j)     ? 0.f : a10 * inv;
    d_w[(i + 1) * 512 + (j + 1)] = (i + 1 == j + 1) ? 0.f : a11 * inv;
}

// ---------------- label = softmax(lat @ fcn_w^T + fcn_b) -------------------
__global__ void label_kernel(const float* __restrict__ fw, const float* __restrict__ fb,
                             float* __restrict__ out) {
    int blk = blockIdx.x;          // images blk*4 .. blk*4+3
    int l = threadIdx.x;           // 0..127
    int lane = l & 31, warp = l >> 5;
    __shared__ float slat[4][512];
    __shared__ float redm[4], reds[4];
    for (int idx = l; idx < 512; idx += 128) {
        int img = idx >> 7, k4 = idx & 127;
        ((float4*)&slat[img][0])[k4] = ((const float4*)(d_fc + (blk * 4 + img) * 512))[k4];
    }
    __syncthreads();
    float acc[4];
    float bias = fb[l];
#pragma unroll
    for (int img = 0; img < 4; img++) acc[img] = bias;
    const float4* fr = (const float4*)(fw + l * 512);
    for (int kc = 0; kc < 16; kc++) {
        float4 wv[8];
#pragma unroll
        for (int c = 0; c < 8; c++) wv[c] = fr[kc * 8 + c];
#pragma unroll
        for (int img = 0; img < 4; img++) {
            const float4* s4 = (const float4*)&slat[img][kc * 32];
#pragma unroll
            for (int c = 0; c < 8; c++) {
                float4 sv = s4[c];
                acc[img] = fmaf(sv.x, wv[c].x, acc[img]);
                acc[img] = fmaf(sv.y, wv[c].y, acc[img]);
                acc[img] = fmaf(sv.z, wv[c].z, acc[img]);
                acc[img] = fmaf(sv.w, wv[c].w, acc[img]);
            }
        }
    }
    for (int img = 0; img < 4; img++) {
        float m = acc[img];
#pragma unroll
        for (int off = 16; off > 0; off >>= 1)
            m = fmaxf(m, __shfl_xor_sync(0xffffffffu, m, off));
        if (lane == 0) redm[warp] = m;
        __syncthreads();
        m = fmaxf(fmaxf(redm[0], redm[1]), fmaxf(redm[2], redm[3]));
        float ex = expf(acc[img] - m);
        float s = ex;
#pragma unroll
        for (int off = 16; off > 0; off >>= 1)
            s += __shfl_xor_sync(0xffffffffu, s, off);
        if (lane == 0) reds[warp] = s;
        __syncthreads();
        s = reds[0] + reds[1] + reds[2] + reds[3];
        out[131072 + (blk * 4 + img) * 128 + l] = ex / s;
        __syncthreads();
    }
}

// ---------------- Hopfield clustering (sparse union-delta) + softmax -------
__global__ void __launch_bounds__(512, 1) cluster_kernel(float* __restrict__ out) {
    __shared__ float coef[512][8];
    __shared__ int   ulist[512];
    __shared__ int   warpcnt[16], warpbase[16];
    __shared__ int   s_nf, doneflag;
    __shared__ float epart[16][8];
    __shared__ float esm[8];
    __shared__ unsigned wA[16], wB[16];
    __shared__ float dots[8][128];

    int t = threadIdx.x;
    int lane = t & 31, warp = t >> 5;
    int row0 = blockIdx.x * 8;
    const float* wc = d_w + t;

    float h[8], sp[8], sp2[8], mins[8], min_e[8];
    const float nanv = __int_as_float(0x7fffffff);

#pragma unroll
    for (int r = 0; r < 8; r++) {
        float v = tanhf(d_fc[(row0 + r) * 512 + t]);
        sp[r] = v;
        sp2[r] = nanv;
        mins[r] = 0.f;
        min_e[r] = INFINITY;
    }
    *(float4*)&coef[t][0] = make_float4(sp[0], sp[1], sp[2], sp[3]);
    *(float4*)&coef[t][4] = make_float4(sp[4], sp[5], sp[6], sp[7]);
    __syncthreads();

    // prologue full GEMV: h = s0 @ w
    {
        u64 hh[4] = {0ull, 0ull, 0ull, 0ull};
#pragma unroll 4
        for (int j = 0; j < 512; j++) {
            u64 wp = bc2(wc[j * 512]);
            ulonglong2 cA = *(const ulonglong2*)&coef[j][0];
            ulonglong2 cB = *(const ulonglong2*)&coef[j][4];
            hh[0] = fma2(wp, cA.x, hh[0]);
            hh[1] = fma2(wp, cA.y, hh[1]);
            hh[2] = fma2(wp, cB.x, hh[2]);
            hh[3] = fma2(wp, cB.y, hh[3]);
        }
#pragma unroll
        for (int q = 0; q < 4; q++) {
            float2 f = up2(hh[q]);
            h[2 * q] = f.x; h[2 * q + 1] = f.y;
        }
    }

    for (int iter = 0; iter < LATENT; iter++) {
        float sn[8], cf[8];
        unsigned a = 0, b = 0;
        bool flip = false;
#pragma unroll
        for (int r = 0; r < 8; r++) {
            float v = fabsf(sp[r]) * sgnf(h[r]);
            sn[r] = v;
            cf[r] = v - sp[r];
            if (cf[r] != 0.f) flip = true;
            if (v == sp[r]) a |= (1u << r);
            if (v == sp2[r]) b |= (1u << r);
        }
        a = __reduce_and_sync(0xffffffffu, a);
        b = __reduce_and_sync(0xffffffffu, b);
        unsigned bal = __ballot_sync(0xffffffffu, flip);
        if (lane == 0) { wA[warp] = a; wB[warp] = b; warpcnt[warp] = __popc(bal); }
        __syncthreads();   // S1
        *(float4*)&coef[t][0] = make_float4(cf[0], cf[1], cf[2], cf[3]);
        *(float4*)&coef[t][4] = make_float4(cf[4], cf[5], cf[6], cf[7]);
        if (t == 0) {
            int accn = 0;
            unsigned A = 0xffu, B = 0xffu;
            for (int q = 0; q < 16; q++) {
                warpbase[q] = accn;
                accn += warpcnt[q];
                A &= wA[q]; B &= wB[q];
            }
            s_nf = accn;
            doneflag = ((A | B) == 0xffu) ? 1 : 0;
        }
        __syncthreads();   // S2
        if (flip) {
            int rank = __popc(bal & ((1u << lane) - 1u));
            ulist[warpbase[warp] + rank] = t;
        }
        __syncthreads();   // S3
        int nf = s_nf;
        int done = doneflag;

        // delta update: h += coef[j] * w[j][t] over union list
        {
            u64 hh[4];
#pragma unroll
            for (int q = 0; q < 4; q++) hh[q] = pk2(h[2 * q], h[2 * q + 1]);
            int i = 0;
            for (; i + 4 <= nf; i += 4) {
                int j0 = ulist[i], j1 = ulist[i + 1], j2 = ulist[i + 2], j3 = ulist[i + 3];
                float w0 = wc[j0 * 512], w1 = wc[j1 * 512];
                float w2 = wc[j2 * 512], w3 = wc[j3 * 512];
                {
                    u64 wp = bc2(w0);
                    ulonglong2 cA = *(const ulonglong2*)&coef[j0][0];
                    ulonglong2 cB = *(const ulonglong2*)&coef[j0][4];
                    hh[0] = fma2(wp, cA.x, hh[0]); hh[1] = fma2(wp, cA.y, hh[1]);
                    hh[2] = fma2(wp, cB.x, hh[2]); hh[3] = fma2(wp, cB.y, hh[3]);
                }
                {
                    u64 wp = bc2(w1);
                    ulonglong2 cA = *(const ulonglong2*)&coef[j1][0];
                    ulonglong2 cB = *(const ulonglong2*)&coef[j1][4];
                    hh[0] = fma2(wp, cA.x, hh[0]); hh[1] = fma2(wp, cA.y, hh[1]);
                    hh[2] = fma2(wp, cB.x, hh[2]); hh[3] = fma2(wp, cB.y, hh[3]);
                }
                {
                    u64 wp = bc2(w2);
                    ulonglong2 cA = *(const ulonglong2*)&coef[j2][0];
                    ulonglong2 cB = *(const ulonglong2*)&coef[j2][4];
                    hh[0] = fma2(wp, cA.x, hh[0]); hh[1] = fma2(wp, cA.y, hh[1]);
                    hh[2] = fma2(wp, cB.x, hh[2]); hh[3] = fma2(wp, cB.y, hh[3]);
                }
                {
                    u64 wp = bc2(w3);
                    ulonglong2 cA = *(const ulonglong2*)&coef[j3][0];
                    ulonglong2 cB = *(const ulonglong2*)&coef[j3][4];
                    hh[0] = fma2(wp, cA.x, hh[0]); hh[1] = fma2(wp, cA.y, hh[1]);
                    hh[2] = fma2(wp, cB.x, hh[2]); hh[3] = fma2(wp, cB.y, hh[3]);
                }
            }
            for (; i < nf; i++) {
                int j = ulist[i];
                u64 wp = bc2(wc[j * 512]);
                ulonglong2 cA = *(const ulonglong2*)&coef[j][0];
                ulonglong2 cB = *(const ulonglong2*)&coef[j][4];
                hh[0] = fma2(wp, cA.x, hh[0]); hh[1] = fma2(wp, cA.y, hh[1]);
                hh[2] = fma2(wp, cB.x, hh[2]); hh[3] = fma2(wp, cB.y, hh[3]);
            }
#pragma unroll
            for (int q = 0; q < 4; q++) {
                float2 f = up2(hh[q]);
                h[2 * q] = f.x; h[2 * q + 1] = f.y;
            }
        }

        // energy e[r] = -sum_t sn[r]*h[r]
        float p[8];
#pragma unroll
        for (int r = 0; r < 8; r++) p[r] = sn[r] * h[r];
#pragma unroll
        for (int r = 0; r < 8; r++) {
#pragma unroll
            for (int off = 16; off > 0; off >>= 1)
                p[r] += __shfl_down_sync(0xffffffffu, p[r], off);
        }
        if (lane == 0) {
#pragma unroll
            for (int r = 0; r < 8; r++) epart[warp][r] = p[r];
        }
        __syncthreads();   // S4
        if (t < 8) {
            float e = 0.f;
            for (int q = 0; q < 16; q++) e += epart[q][t];
            esm[t] = -e;
        }
        __syncthreads();   // S5
#pragma unroll
        for (int r = 0; r < 8; r++) {
            float e = esm[r];
            if (e < min_e[r]) { min_e[r] = e; mins[r] = sn[r]; }
            sp2[r] = sp[r]; sp[r] = sn[r];
        }
        if (done) break;
    }

    // ---------------- epilogue: out = softmax(|min_s @ rep^T|) -------------
    __syncthreads();
    *(float4*)&coef[t][0] = make_float4(mins[0], mins[1], mins[2], mins[3]);
    *(float4*)&coef[t][4] = make_float4(mins[4], mins[5], mins[6], mins[7]);
    __syncthreads();

    int l = t >> 2, q = t & 3;
#pragma unroll
    for (int r = 0; r < 8; r++) {
        const float4* rp = (const float4*)(d_rep + l * 512 + q * 128);
        float v = 0.f;
#pragma unroll 8
        for (int i4 = 0; i4 < 32; i4++) {
            float4 rv = rp[i4];
            int j = q * 128 + i4 * 4;
            v = fmaf(coef[j + 0][r], rv.x, v);
            v = fmaf(coef[j + 1][r], rv.y, v);
            v = fmaf(coef[j + 2][r], rv.z, v);
            v = fmaf(coef[j + 3][r], rv.w, v);
        }
        v += __shfl_xor_sync(0xffffffffu, v, 1);
        v += __shfl_xor_sync(0xffffffffu, v, 2);
        if (q == 0) dots[r][l] = fabsf(v);
    }
    __syncthreads();

    if (warp < 8) {
        int r = warp;
        float v0 = dots[r][lane], v1 = dots[r][lane + 32];
        float v2 = dots[r][lane + 64], v3 = dots[r][lane + 96];
        float m = fmaxf(fmaxf(v0, v1), fmaxf(v2, v3));
#pragma unroll
        for (int off = 16; off > 0; off >>= 1)
            m = fmaxf(m, __shfl_xor_sync(0xffffffffu, m, off));
        float e0 = expf(v0 - m), e1 = expf(v1 - m), e2 = expf(v2 - m), e3 = expf(v3 - m);
        float s = e0 + e1 + e2 + e3;
#pragma unroll
        for (int off = 16; off > 0; off >>= 1)
            s += __shfl_xor_sync(0xffffffffu, s, off);
        float inv = 1.f / s;
        float* o = out + (row0 + r) * 128;
        o[lane] = e0 * inv;
        o[lane + 32] = e1 * inv;
        o[lane + 64] = e2 * inv;
        o[lane + 96] = e3 * inv;
    }
}

// ---------------------------------------------------------------------------
extern "C" void kernel_launch(void* const* d_in, const int* in_sizes, int n_in,
                              void* d_out, int out_size) {
    const float* image     = (const float*)d_in[0];
    const float* label_img = (const float*)d_in[1];
    const float* c1w       = (const float*)d_in[2];
    const float* c1b       = (const float*)d_in[3];
    const float* c2w       = (const float*)d_in[4];
    const float* c2b       = (const float*)d_in[5];
    const float* f1w       = (const float*)d_in[6];
    const float* f1b       = (const float*)d_in[7];
    const float* fnw       = (const float*)d_in[8];
    const float* fnb       = (const float*)d_in[9];
    float* out = (float*)d_out;

    // launch index 3 is the ncu-profiled slot -> fc1 (v2) this round
    transpose_w2_kernel<<<200, 256>>>(c2w);               // 0
    conv1_kernel<<<N_TOT, 256>>>(image, label_img, c1w, c1b); // 1
    conv2_kernel<<<N_TOT, 392>>>(c2b);                    // 2
    fc1_kernel<<<dim3(36, 8), 256>>>(f1w, f1b);           // 3  <- profiled
    label_kernel<<<256, 128>>>(fnw, fnb, out);
    tanh_rep_kernel<<<128, 512>>>();
    rho_kernel<<<1, 32>>>();
    hopw_kernel<<<dim3(16, 16), 256>>>();
    cluster_kernel<<<128, 512>>>(out);
}

// round 14
// speedup vs baseline: 1.2474x; 1.0694x over previous
#include <cuda_runtime.h>
#include <math.h>

#define N_IMG 1024
#define N_LAB 128
#define N_TOT 1152
#define LATENT 512
#define NLABEL 128

typedef unsigned long long u64;

// ---- packed f32x2 helpers (lanewise rn-FMA; bitwise == two scalar fmaf) ----
__device__ __forceinline__ u64 pk2(float lo, float hi) {
    u64 r; asm("mov.b64 %0, {%1, %2};" : "=l"(r) : "f"(lo), "f"(hi)); return r;
}
__device__ __forceinline__ u64 bc2(float x) { return pk2(x, x); }
__device__ __forceinline__ float2 up2(u64 v) {
    float2 f; asm("mov.b64 {%0, %1}, %2;" : "=f"(f.x), "=f"(f.y) : "l"(v)); return f;
}
__device__ __forceinline__ u64 fma2(u64 a, u64 b, u64 c) {
    u64 d; asm("fma.rn.f32x2 %0, %1, %2, %3;" : "=l"(d) : "l"(a), "l"(b), "l"(c)); return d;
}

// ---------------- scratch (device globals; no allocation allowed) ----------
__device__ __align__(16) float d_pool1[N_TOT * 32 * 14 * 14];
__device__ __align__(16) float d_pool2[N_TOT * 3136];
__device__ __align__(16) float d_fc[N_TOT * LATENT];
__device__ __align__(16) float d_rep[N_LAB * LATENT];
__device__ __align__(16) float d_w[LATENT * LATENT];
__device__ __align__(16) float d_w2[32 * 25 * 64];   // conv2 weights [ic][k][oc]
__device__ float d_rhopart[N_LAB];
__device__ float d_rho[1];

__device__ __forceinline__ float sgnf(float x) {
    return (x > 0.f) ? 1.f : ((x < 0.f) ? -1.f : 0.f);
}

// ---------------- one-time conv2 weight transpose: [oc][ic][k] -> [ic][k][oc]
__global__ void transpose_w2_kernel(const float* __restrict__ w) {
    int idx = blockIdx.x * 256 + threadIdx.x;   // 51200 total
    if (idx < 51200) {
        int ic = idx / 1600, rem = idx % 1600;
        int k = rem >> 6, oc = rem & 63;
        d_w2[idx] = w[oc * 800 + ic * 25 + k];
    }
}

// ---------------- conv1 + relu + pool : [N,1,28,28] -> [N,32,14,14] --------
__global__ void conv1_kernel(const float* __restrict__ img, const float* __restrict__ lab,
                             const float* __restrict__ w, const float* __restrict__ b) {
    int n = blockIdx.x;
    const float* src = (n < N_IMG) ? (img + n * 784) : (lab + (n - N_IMG) * 784);
    __shared__ float sin_[32 * 32];
    __shared__ float sw[800];
    __shared__ float sb[32];
    int t = threadIdx.x;
    for (int idx = t; idx < 1024; idx += 256) {
        int y = idx >> 5, x = idx & 31;
        int iy = y - 2, ix = x - 2;
        float v = 0.f;
        if (iy >= 0 && iy < 28 && ix >= 0 && ix < 28) v = src[iy * 28 + ix];
        sin_[idx] = v;
    }
    for (int idx = t; idx < 800; idx += 256) sw[idx] = w[idx];
    if (t < 32) sb[t] = b[t];
    __syncthreads();
    int oc = t >> 3, tp = t & 7;
    float wr[25];
#pragma unroll
    for (int u = 0; u < 25; u++) wr[u] = sw[oc * 25 + u];
    float bias = sb[oc];
    for (int pos = tp; pos < 196; pos += 8) {
        int py = pos / 14, px = pos % 14;
        float win[36];
        int base = (2 * py) * 32 + 2 * px;
#pragma unroll
        for (int wy = 0; wy < 6; wy++)
#pragma unroll
            for (int wx = 0; wx < 6; wx++)
                win[wy * 6 + wx] = sin_[base + wy * 32 + wx];
        u64 pp[6][5];
#pragma unroll
        for (int ky = 0; ky < 6; ky++)
#pragma unroll
            for (int kx = 0; kx < 5; kx++) pp[ky][kx] = pk2(win[ky * 6 + kx], win[ky * 6 + kx + 1]);
        u64 A0 = 0ull, A1 = 0ull;
#pragma unroll
        for (int ky = 0; ky < 5; ky++)
#pragma unroll
            for (int kx = 0; kx < 5; kx++) {
                u64 wp = bc2(wr[ky * 5 + kx]);
                A0 = fma2(wp, pp[ky][kx], A0);
                A1 = fma2(wp, pp[ky + 1][kx], A1);
            }
        float2 f0 = up2(A0), f1 = up2(A1);
        float m = fmaxf(fmaxf(fmaxf(f0.x + bias, 0.f), fmaxf(f0.y + bias, 0.f)),
                        fmaxf(fmaxf(f1.x + bias, 0.f), fmaxf(f1.y + bias, 0.f)));
        d_pool1[n * 6272 + oc * 196 + pos] = m;
    }
}

// ---------------- conv2 + relu + pool : [N,32,14,14] -> [N,64,7,7] ---------
// R10 version (best measured: 537us). 392 thr = 49 pos x 8 oc-groups; weights
// read directly from pre-transposed d_w2[ic][k][oc] as warp-UNIFORM LDG.128.
__global__ void conv2_kernel(const float* __restrict__ b) {
    int n = blockIdx.x;
    __shared__ float sin_[32 * 18 * 18];  // 10368 floats
    int t = threadIdx.x;                  // 392 threads
    for (int idx = t; idx < 10368; idx += 392) {
        int ic = idx / 324, rem = idx % 324;
        int y = rem / 18, x = rem % 18;
        int iy = y - 2, ix = x - 2;
        float v = 0.f;
        if (iy >= 0 && iy < 14 && ix >= 0 && ix < 14)
            v = d_pool1[n * 6272 + ic * 196 + iy * 14 + ix];
        sin_[idx] = v;
    }
    __syncthreads();                      // the only barrier

    int pos = t % 49, grp = t / 49;       // 49 positions x 8 oc-groups
    int py = pos / 7, px = pos % 7;
    u64 acc[4][4];                        // [oc-pair][subpos 00,01,10,11]
#pragma unroll
    for (int p = 0; p < 4; p++)
#pragma unroll
        for (int q = 0; q < 4; q++) acc[p][q] = 0ull;

    const float* wg = d_w2 + grp * 8;     // [ic][k][oc] slice for this group
    for (int ic = 0; ic < 32; ic++) {
        float win[36];
        int base = ic * 324 + (2 * py) * 18 + 2 * px;   // even -> float2-aligned
#pragma unroll
        for (int wy = 0; wy < 6; wy++) {
            float2 va = *(const float2*)&sin_[base + wy * 18 + 0];
            float2 vb = *(const float2*)&sin_[base + wy * 18 + 2];
            float2 vc = *(const float2*)&sin_[base + wy * 18 + 4];
            win[wy * 6 + 0] = va.x; win[wy * 6 + 1] = va.y;
            win[wy * 6 + 2] = vb.x; win[wy * 6 + 3] = vb.y;
            win[wy * 6 + 4] = vc.x; win[wy * 6 + 5] = vc.y;
        }
        const float* wic = wg + ic * 1600;
#pragma unroll
        for (int ky = 0; ky < 5; ky++)
#pragma unroll
            for (int kx = 0; kx < 5; kx++) {
                const float* swk = wic + (ky * 5 + kx) * 64;   // 16B-aligned
                ulonglong2 wp01 = *(const ulonglong2*)&swk[0];
                ulonglong2 wp23 = *(const ulonglong2*)&swk[4];
                u64 wp0 = wp01.x, wp1 = wp01.y, wp2 = wp23.x, wp3 = wp23.y;
                u64 b00 = bc2(win[ky * 6 + kx]);
                u64 b01 = bc2(win[ky * 6 + kx + 1]);
                u64 b10 = bc2(win[(ky + 1) * 6 + kx]);
                u64 b11 = bc2(win[(ky + 1) * 6 + kx + 1]);
                acc[0][0] = fma2(wp0, b00, acc[0][0]);
                acc[0][1] = fma2(wp0, b01, acc[0][1]);
                acc[0][2] = fma2(wp0, b10, acc[0][2]);
                acc[0][3] = fma2(wp0, b11, acc[0][3]);
                acc[1][0] = fma2(wp1, b00, acc[1][0]);
                acc[1][1] = fma2(wp1, b01, acc[1][1]);
                acc[1][2] = fma2(wp1, b10, acc[1][2]);
                acc[1][3] = fma2(wp1, b11, acc[1][3]);
                acc[2][0] = fma2(wp2, b00, acc[2][0]);
                acc[2][1] = fma2(wp2, b01, acc[2][1]);
                acc[2][2] = fma2(wp2, b10, acc[2][2]);
                acc[2][3] = fma2(wp2, b11, acc[2][3]);
                acc[3][0] = fma2(wp3, b00, acc[3][0]);
                acc[3][1] = fma2(wp3, b01, acc[3][1]);
                acc[3][2] = fma2(wp3, b10, acc[3][2]);
                acc[3][3] = fma2(wp3, b11, acc[3][3]);
            }
    }
#pragma unroll
    for (int p = 0; p < 4; p++) {
        int oc0 = grp * 8 + 2 * p;
        float bias0 = b[oc0], bias1 = b[oc0 + 1];
        float2 v0 = up2(acc[p][0]), v1 = up2(acc[p][1]);
        float2 v2 = up2(acc[p][2]), v3 = up2(acc[p][3]);
        float m0 = fmaxf(fmaxf(fmaxf(v0.x + bias0, 0.f), fmaxf(v1.x + bias0, 0.f)),
                         fmaxf(fmaxf(v2.x + bias0, 0.f), fmaxf(v3.x + bias0, 0.f)));
        float m1 = fmaxf(fmaxf(fmaxf(v0.y + bias1, 0.f), fmaxf(v1.y + bias1, 0.f)),
                         fmaxf(fmaxf(v2.y + bias1, 0.f), fmaxf(v3.y + bias1, 0.f)));
        d_pool2[n * 3136 + oc0 * 49 + pos] = m0;
        d_pool2[n * 3136 + (oc0 + 1) * 49 + pos] = m1;
    }
}

// ---------------- fc1: [1152,3136] @ [512,3136]^T + b -> d_fc --------------
// v3: R12's 64x64 tile / 4x4-per-thread shape (balanced 6 LDS : 8 FFMA2 per
// kk) + R13's double-buffered smem (1 barrier/iter, prefetch overlaps
// compute). Per-output accumulation order unchanged (k ascending, cols
// paired (0,1)/(2,3)).
__global__ void __launch_bounds__(256, 1) fc1_kernel(const float* __restrict__ fw,
                                                     const float* __restrict__ fb) {
    __shared__ float As[2][32][66];
    __shared__ float Bs[2][32][66];
    int t = threadIdx.x;
    int tx = t & 15, ty = t >> 4;
    int m0 = blockIdx.x * 64;
    int n0 = blockIdx.y * 64;

    u64 acc[4][2];
#pragma unroll
    for (int i = 0; i < 4; i++) { acc[i][0] = 0ull; acc[i][1] = 0ull; }

    // loader mapping: ids 0..511 -> row = id>>3 (0..63), k4 = id&7
    // ---- load tile kt=0 into buf 0
#pragma unroll
    for (int u = 0; u < 2; u++) {
        int id = t + u * 256;
        int row = id >> 3, k4 = id & 7;
        float4 va = *(const float4*)&d_pool2[(m0 + row) * 3136 + k4 * 4];
        As[0][k4 * 4 + 0][row] = va.x;
        As[0][k4 * 4 + 1][row] = va.y;
        As[0][k4 * 4 + 2][row] = va.z;
        As[0][k4 * 4 + 3][row] = va.w;
        float4 vb = *(const float4*)&fw[(n0 + row) * 3136 + k4 * 4];
        Bs[0][k4 * 4 + 0][row] = vb.x;
        Bs[0][k4 * 4 + 1][row] = vb.y;
        Bs[0][k4 * 4 + 2][row] = vb.z;
        Bs[0][k4 * 4 + 3][row] = vb.w;
    }
    __syncthreads();

    for (int kt = 0; kt < 98; kt++) {
        int cur = kt & 1;
        if (kt < 97) {                 // prefetch next tile into the other buf
            int nxt = cur ^ 1;
            int k0 = (kt + 1) * 32;
#pragma unroll
            for (int u = 0; u < 2; u++) {
                int id = t + u * 256;
                int row = id >> 3, k4 = id & 7;
                float4 va = *(const float4*)&d_pool2[(m0 + row) * 3136 + k0 + k4 * 4];
                As[nxt][k4 * 4 + 0][row] = va.x;
                As[nxt][k4 * 4 + 1][row] = va.y;
                As[nxt][k4 * 4 + 2][row] = va.z;
                As[nxt][k4 * 4 + 3][row] = va.w;
                float4 vb = *(const float4*)&fw[(n0 + row) * 3136 + k0 + k4 * 4];
                Bs[nxt][k4 * 4 + 0][row] = vb.x;
                Bs[nxt][k4 * 4 + 1][row] = vb.y;
                Bs[nxt][k4 * 4 + 2][row] = vb.z;
                Bs[nxt][k4 * 4 + 3][row] = vb.w;
            }
        }
#pragma unroll
        for (int kk = 0; kk < 32; kk++) {
            u64 b01 = *(const u64*)&Bs[cur][kk][tx * 4];
            u64 b23 = *(const u64*)&Bs[cur][kk][tx * 4 + 2];
#pragma unroll
            for (int i = 0; i < 4; i++) {
                u64 ap = bc2(As[cur][kk][ty * 4 + i]);
                acc[i][0] = fma2(ap, b01, acc[i][0]);
                acc[i][1] = fma2(ap, b23, acc[i][1]);
            }
        }
        __syncthreads();               // next buf filled AND cur free for reuse
    }
#pragma unroll
    for (int i = 0; i < 4; i++) {
        int m = m0 + ty * 4 + i;
        float2 c01 = up2(acc[i][0]), c23 = up2(acc[i][1]);
        int nn = n0 + tx * 4;
        d_fc[m * 512 + nn + 0] = c01.x + fb[nn + 0];
        d_fc[m * 512 + nn + 1] = c01.y + fb[nn + 1];
        d_fc[m * 512 + nn + 2] = c23.x + fb[nn + 2];
        d_fc[m * 512 + nn + 3] = c23.y + fb[nn + 3];
    }
}

// ---------------- rep = tanh(fc rows 1024..1151) + rho partial sums --------
__global__ void tanh_rep_kernel() {
    int bb = blockIdx.x;
    int t = threadIdx.x;
    float v = tanhf(d_fc[(N_IMG + bb) * LATENT + t]);
    d_rep[bb * LATENT + t] = v;
    float s = v;
#pragma unroll
    for (int off = 16; off > 0; off >>= 1) s += __shfl_down_sync(0xffffffffu, s, off);
    __shared__ float ws[16];
    if ((t & 31) == 0) ws[t >> 5] = s;
    __syncthreads();
    if (t == 0) {
        float tot = 0.f;
        for (int i = 0; i < 16; i++) tot += ws[i];
        d_rhopart[bb] = tot;
    }
}

__global__ void rho_kernel() {
    if (threadIdx.x == 0) {
        float s = 0.f;
        for (int i = 0; i < 128; i++) s += d_rhopart[i];
        d_rho[0] = s / 65536.0f;
    }
}

// ---------------- Hopfield W = ((rep-rho)^T (rep-rho)) * (1-I) / 128 -------
__global__ void hopw_kernel() {
    __shared__ float ti[128][32];
    __shared__ float tj[128][32];
    float rho = d_rho[0];
    int i0 = blockIdx.x * 32, j0 = blockIdx.y * 32;
    int t = threadIdx.x;
    for (int idx = t; idx < 4096; idx += 256) {
        int bb = idx >> 5, c = idx & 31;
        ti[bb][c] = d_rep[bb * 512 + i0 + c] - rho;
        tj[bb][c] = d_rep[bb * 512 + j0 + c] - rho;
    }
    __syncthreads();
    int tx = t & 15, ty = t >> 4;
    float a00 = 0.f, a01 = 0.f, a10 = 0.f, a11 = 0.f;
    for (int bb = 0; bb < 128; bb++) {
        float x0 = ti[bb][tx * 2], x1 = ti[bb][tx * 2 + 1];
        float y0 = tj[bb][ty * 2], y1 = tj[bb][ty * 2 + 1];
        a00 = fmaf(x0, y0, a00); a01 = fmaf(x0, y1, a01);
        a10 = fmaf(x1, y0, a10); a11 = fmaf(x1, y1, a11);
    }
    const float inv = 1.f / 128.f;
    int i = i0 + tx * 2, j = j0 + ty * 2;
    d_w[i * 512 + j]             = (i == j)         ? 0.f : a00 * inv;
    d_w[i * 512 + (j + 1)]       = (i == j + 1)     ? 0.f : a01 * inv;
    d_w[(i + 1) * 512 + j]       = (i + 1 == j)     ? 0.f : a10 * inv;
    d_w[(i + 1) * 512 + (j + 1)] = (i + 1 == j + 1) ? 0.f : a11 * inv;
}

// ---------------- label = softmax(lat @ fcn_w^T + fcn_b) -------------------
__global__ void label_kernel(const float* __restrict__ fw, const float* __restrict__ fb,
                             float* __restrict__ out) {
    int blk = blockIdx.x;          // images blk*4 .. blk*4+3
    int l = threadIdx.x;           // 0..127
    int lane = l & 31, warp = l >> 5;
    __shared__ float slat[4][512];
    __shared__ float redm[4], reds[4];
    for (int idx = l; idx < 512; idx += 128) {
        int img = idx >> 7, k4 = idx & 127;
        ((float4*)&slat[img][0])[k4] = ((const float4*)(d_fc + (blk * 4 + img) * 512))[k4];
    }
    __syncthreads();
    float acc[4];
    float bias = fb[l];
#pragma unroll
    for (int img = 0; img < 4; img++) acc[img] = bias;
    const float4* fr = (const float4*)(fw + l * 512);
    for (int kc = 0; kc < 16; kc++) {
        float4 wv[8];
#pragma unroll
        for (int c = 0; c < 8; c++) wv[c] = fr[kc * 8 + c];
#pragma unroll
        for (int img = 0; img < 4; img++) {
            const float4* s4 = (const float4*)&slat[img][kc * 32];
#pragma unroll
            for (int c = 0; c < 8; c++) {
                float4 sv = s4[c];
                acc[img] = fmaf(sv.x, wv[c].x, acc[img]);
                acc[img] = fmaf(sv.y, wv[c].y, acc[img]);
                acc[img] = fmaf(sv.z, wv[c].z, acc[img]);
                acc[img] = fmaf(sv.w, wv[c].w, acc[img]);
            }
        }
    }
    for (int img = 0; img < 4; img++) {
        float m = acc[img];
#pragma unroll
        for (int off = 16; off > 0; off >>= 1)
            m = fmaxf(m, __shfl_xor_sync(0xffffffffu, m, off));
        if (lane == 0) redm[warp] = m;
        __syncthreads();
        m = fmaxf(fmaxf(redm[0], redm[1]), fmaxf(redm[2], redm[3]));
        float ex = expf(acc[img] - m);
        float s = ex;
#pragma unroll
        for (int off = 16; off > 0; off >>= 1)
            s += __shfl_xor_sync(0xffffffffu, s, off);
        if (lane == 0) reds[warp] = s;
        __syncthreads();
        s = reds[0] + reds[1] + reds[2] + reds[3];
        out[131072 + (blk * 4 + img) * 128 + l] = ex / s;
        __syncthreads();
    }
}

// ---------------- Hopfield clustering (sparse union-delta) + softmax -------
__global__ void __launch_bounds__(512, 1) cluster_kernel(float* __restrict__ out) {
    __shared__ float coef[512][8];
    __shared__ int   ulist[512];
    __shared__ int   warpcnt[16], warpbase[16];
    __shared__ int   s_nf, doneflag;
    __shared__ float epart[16][8];
    __shared__ float esm[8];
    __shared__ unsigned wA[16], wB[16];
    __shared__ float dots[8][128];

    int t = threadIdx.x;
    int lane = t & 31, warp = t >> 5;
    int row0 = blockIdx.x * 8;
    const float* wc = d_w + t;

    float h[8], sp[8], sp2[8], mins[8], min_e[8];
    const float nanv = __int_as_float(0x7fffffff);

#pragma unroll
    for (int r = 0; r < 8; r++) {
        float v = tanhf(d_fc[(row0 + r) * 512 + t]);
        sp[r] = v;
        sp2[r] = nanv;
        mins[r] = 0.f;
        min_e[r] = INFINITY;
    }
    *(float4*)&coef[t][0] = make_float4(sp[0], sp[1], sp[2], sp[3]);
    *(float4*)&coef[t][4] = make_float4(sp[4], sp[5], sp[6], sp[7]);
    __syncthreads();

    // prologue full GEMV: h = s0 @ w
    {
        u64 hh[4] = {0ull, 0ull, 0ull, 0ull};
#pragma unroll 4
        for (int j = 0; j < 512; j++) {
            u64 wp = bc2(wc[j * 512]);
            ulonglong2 cA = *(const ulonglong2*)&coef[j][0];
            ulonglong2 cB = *(const ulonglong2*)&coef[j][4];
            hh[0] = fma2(wp, cA.x, hh[0]);
            hh[1] = fma2(wp, cA.y, hh[1]);
            hh[2] = fma2(wp, cB.x, hh[2]);
            hh[3] = fma2(wp, cB.y, hh[3]);
        }
#pragma unroll
        for (int q = 0; q < 4; q++) {
            float2 f = up2(hh[q]);
            h[2 * q] = f.x; h[2 * q + 1] = f.y;
        }
    }

    for (int iter = 0; iter < LATENT; iter++) {
        float sn[8], cf[8];
        unsigned a = 0, b = 0;
        bool flip = false;
#pragma unroll
        for (int r = 0; r < 8; r++) {
            float v = fabsf(sp[r]) * sgnf(h[r]);
            sn[r] = v;
            cf[r] = v - sp[r];
            if (cf[r] != 0.f) flip = true;
            if (v == sp[r]) a |= (1u << r);
            if (v == sp2[r]) b |= (1u << r);
        }
        a = __reduce_and_sync(0xffffffffu, a);
        b = __reduce_and_sync(0xffffffffu, b);
        unsigned bal = __ballot_sync(0xffffffffu, flip);
        if (lane == 0) { wA[warp] = a; wB[warp] = b; warpcnt[warp] = __popc(bal); }
        __syncthreads();   // S1
        *(float4*)&coef[t][0] = make_float4(cf[0], cf[1], cf[2], cf[3]);
        *(float4*)&coef[t][4] = make_float4(cf[4], cf[5], cf[6], cf[7]);
        if (t == 0) {
            int accn = 0;
            unsigned A = 0xffu, B = 0xffu;
            for (int q = 0; q < 16; q++) {
                warpbase[q] = accn;
                accn += warpcnt[q];
                A &= wA[q]; B &= wB[q];
            }
            s_nf = accn;
            doneflag = ((A | B) == 0xffu) ? 1 : 0;
        }
        __syncthreads();   // S2
        if (flip) {
            int rank = __popc(bal & ((1u << lane) - 1u));
            ulist[warpbase[warp] + rank] = t;
        }
        __syncthreads();   // S3
        int nf = s_nf;
        int done = doneflag;

        // delta update: h += coef[j] * w[j][t] over union list
        {
            u64 hh[4];
#pragma unroll
            for (int q = 0; q < 4; q++) hh[q] = pk2(h[2 * q], h[2 * q + 1]);
            int i = 0;
            for (; i + 4 <= nf; i += 4) {
                int j0 = ulist[i], j1 = ulist[i + 1], j2 = ulist[i + 2], j3 = ulist[i + 3];
                float w0 = wc[j0 * 512], w1 = wc[j1 * 512];
                float w2 = wc[j2 * 512], w3 = wc[j3 * 512];
                {
                    u64 wp = bc2(w0);
                    ulonglong2 cA = *(const ulonglong2*)&coef[j0][0];
                    ulonglong2 cB = *(const ulonglong2*)&coef[j0][4];
                    hh[0] = fma2(wp, cA.x, hh[0]); hh[1] = fma2(wp, cA.y, hh[1]);
                    hh[2] = fma2(wp, cB.x, hh[2]); hh[3] = fma2(wp, cB.y, hh[3]);
                }
                {
                    u64 wp = bc2(w1);
                    ulonglong2 cA = *(const ulonglong2*)&coef[j1][0];
                    ulonglong2 cB = *(const ulonglong2*)&coef[j1][4];
                    hh[0] = fma2(wp, cA.x, hh[0]); hh[1] = fma2(wp, cA.y, hh[1]);
                    hh[2] = fma2(wp, cB.x, hh[2]); hh[3] = fma2(wp, cB.y, hh[3]);
                }
                {
                    u64 wp = bc2(w2);
                    ulonglong2 cA = *(const ulonglong2*)&coef[j2][0];
                    ulonglong2 cB = *(const ulonglong2*)&coef[j2][4];
                    hh[0] = fma2(wp, cA.x, hh[0]); hh[1] = fma2(wp, cA.y, hh[1]);
                    hh[2] = fma2(wp, cB.x, hh[2]); hh[3] = fma2(wp, cB.y, hh[3]);
                }
                {
                    u64 wp = bc2(w3);
                    ulonglong2 cA = *(const ulonglong2*)&coef[j3][0];
                    ulonglong2 cB = *(const ulonglong2*)&coef[j3][4];
                    hh[0] = fma2(wp, cA.x, hh[0]); hh[1] = fma2(wp, cA.y, hh[1]);
                    hh[2] = fma2(wp, cB.x, hh[2]); hh[3] = fma2(wp, cB.y, hh[3]);
                }
            }
            for (; i < nf; i++) {
                int j = ulist[i];
                u64 wp = bc2(wc[j * 512]);
                ulonglong2 cA = *(const ulonglong2*)&coef[j][0];
                ulonglong2 cB = *(const ulonglong2*)&coef[j][4];
                hh[0] = fma2(wp, cA.x, hh[0]); hh[1] = fma2(wp, cA.y, hh[1]);
                hh[2] = fma2(wp, cB.x, hh[2]); hh[3] = fma2(wp, cB.y, hh[3]);
            }
#pragma unroll
            for (int q = 0; q < 4; q++) {
                float2 f = up2(hh[q]);
                h[2 * q] = f.x; h[2 * q + 1] = f.y;
            }
        }

        // energy e[r] = -sum_t sn[r]*h[r]
        float p[8];
#pragma unroll
        for (int r = 0; r < 8; r++) p[r] = sn[r] * h[r];
#pragma unroll
        for (int r = 0; r < 8; r++) {
#pragma unroll
            for (int off = 16; off > 0; off >>= 1)
                p[r] += __shfl_down_sync(0xffffffffu, p[r], off);
        }
        if (lane == 0) {
#pragma unroll
            for (int r = 0; r < 8; r++) epart[warp][r] = p[r];
        }
        __syncthreads();   // S4
        if (t < 8) {
            float e = 0.f;
            for (int q = 0; q < 16; q++) e += epart[q][t];
            esm[t] = -e;
        }
        __syncthreads();   // S5
#pragma unroll
        for (int r = 0; r < 8; r++) {
            float e = esm[r];
            if (e < min_e[r]) { min_e[r] = e; mins[r] = sn[r]; }
            sp2[r] = sp[r]; sp[r] = sn[r];
        }
        if (done) break;
    }

    // ---------------- epilogue: out = softmax(|min_s @ rep^T|) -------------
    __syncthreads();
    *(float4*)&coef[t][0] = make_float4(mins[0], mins[1], mins[2], mins[3]);
    *(float4*)&coef[t][4] = make_float4(mins[4], mins[5], mins[6], mins[7]);
    __syncthreads();

    int l = t >> 2, q = t & 3;
#pragma unroll
    for (int r = 0; r < 8; r++) {
        const float4* rp = (const float4*)(d_rep + l * 512 + q * 128);
        float v = 0.f;
#pragma unroll 8
        for (int i4 = 0; i4 < 32; i4++) {
            float4 rv = rp[i4];
            int j = q * 128 + i4 * 4;
            v = fmaf(coef[j + 0][r], rv.x, v);
            v = fmaf(coef[j + 1][r], rv.y, v);
            v = fmaf(coef[j + 2][r], rv.z, v);
            v = fmaf(coef[j + 3][r], rv.w, v);
        }
        v += __shfl_xor_sync(0xffffffffu, v, 1);
        v += __shfl_xor_sync(0xffffffffu, v, 2);
        if (q == 0) dots[r][l] = fabsf(v);
    }
    __syncthreads();

    if (warp < 8) {
        int r = warp;
        float v0 = dots[r][lane], v1 = dots[r][lane + 32];
        float v2 = dots[r][lane + 64], v3 = dots[r][lane + 96];
        float m = fmaxf(fmaxf(v0, v1), fmaxf(v2, v3));
#pragma unroll
        for (int off = 16; off > 0; off >>= 1)
            m = fmaxf(m, __shfl_xor_sync(0xffffffffu, m, off));
        float e0 = expf(v0 - m), e1 = expf(v1 - m), e2 = expf(v2 - m), e3 = expf(v3 - m);
        float s = e0 + e1 + e2 + e3;
#pragma unroll
        for (int off = 16; off > 0; off >>= 1)
            s += __shfl_xor_sync(0xffffffffu, s, off);
        float inv = 1.f / s;
        float* o = out + (row0 + r) * 128;
        o[lane] = e0 * inv;
        o[lane + 32] = e1 * inv;
        o[lane + 64] = e2 * inv;
        o[lane + 96] = e3 * inv;
    }
}

// ---------------------------------------------------------------------------
extern "C" void kernel_launch(void* const* d_in, const int* in_sizes, int n_in,
                              void* d_out, int out_size) {
    const float* image     = (const float*)d_in[0];
    const float* label_img = (const float*)d_in[1];
    const float* c1w       = (const float*)d_in[2];
    const float* c1b       = (const float*)d_in[3];
    const float* c2w       = (const float*)d_in[4];
    const float* c2b       = (const float*)d_in[5];
    const float* f1w       = (const float*)d_in[6];
    const float* f1b       = (const float*)d_in[7];
    const float* fnw       = (const float*)d_in[8];
    const float* fnb       = (const float*)d_in[9];
    float* out = (float*)d_out;

    // launch index 3 is the ncu-profiled slot -> fc1 (v3) this round
    transpose_w2_kernel<<<200, 256>>>(c2w);               // 0
    conv1_kernel<<<N_TOT, 256>>>(image, label_img, c1w, c1b); // 1
    conv2_kernel<<<N_TOT, 392>>>(c2b);                    // 2
    fc1_kernel<<<dim3(18, 8), 256>>>(f1w, f1b);           // 3  <- profiled
    label_kernel<<<256, 128>>>(fnw, fnb, out);
    tanh_rep_kernel<<<128, 512>>>();
    rho_kernel<<<1, 32>>>();
    hopw_kernel<<<dim3(16, 16), 256>>>();
    cluster_kernel<<<128, 512>>>(out);
}

// round 15
// speedup vs baseline: 1.2732x; 1.0207x over previous
#include <cuda_runtime.h>
#include <math.h>

#define N_IMG 1024
#define N_LAB 128
#define N_TOT 1152
#define LATENT 512
#define NLABEL 128

typedef unsigned long long u64;

// ---- packed f32x2 helpers (lanewise rn-FMA; bitwise == two scalar fmaf) ----
__device__ __forceinline__ u64 pk2(float lo, float hi) {
    u64 r; asm("mov.b64 %0, {%1, %2};" : "=l"(r) : "f"(lo), "f"(hi)); return r;
}
__device__ __forceinline__ u64 bc2(float x) { return pk2(x, x); }
__device__ __forceinline__ float2 up2(u64 v) {
    float2 f; asm("mov.b64 {%0, %1}, %2;" : "=f"(f.x), "=f"(f.y) : "l"(v)); return f;
}
__device__ __forceinline__ u64 fma2(u64 a, u64 b, u64 c) {
    u64 d; asm("fma.rn.f32x2 %0, %1, %2, %3;" : "=l"(d) : "l"(a), "l"(b), "l"(c)); return d;
}

// ---------------- scratch (device globals; no allocation allowed) ----------
__device__ __align__(16) float d_pool1[N_TOT * 32 * 14 * 14];
__device__ __align__(16) float d_pool2[N_TOT * 3136];
__device__ __align__(16) float d_fc[N_TOT * LATENT];
__device__ __align__(16) float d_fcp[2 * N_TOT * LATENT];   // fc1 k-split partials
__device__ __align__(16) float d_rep[N_LAB * LATENT];
__device__ __align__(16) float d_w[LATENT * LATENT];
__device__ __align__(16) float d_w2[32 * 25 * 64];   // conv2 weights [ic][k][oc]
__device__ float d_rhopart[N_LAB];
__device__ float d_rho[1];

__device__ __forceinline__ float sgnf(float x) {
    return (x > 0.f) ? 1.f : ((x < 0.f) ? -1.f : 0.f);
}

// ---------------- one-time conv2 weight transpose: [oc][ic][k] -> [ic][k][oc]
__global__ void transpose_w2_kernel(const float* __restrict__ w) {
    int idx = blockIdx.x * 256 + threadIdx.x;   // 51200 total
    if (idx < 51200) {
        int ic = idx / 1600, rem = idx % 1600;
        int k = rem >> 6, oc = rem & 63;
        d_w2[idx] = w[oc * 800 + ic * 25 + k];
    }
}

// ---------------- conv1 + relu + pool : [N,1,28,28] -> [N,32,14,14] --------
__global__ void conv1_kernel(const float* __restrict__ img, const float* __restrict__ lab,
                             const float* __restrict__ w, const float* __restrict__ b) {
    int n = blockIdx.x;
    const float* src = (n < N_IMG) ? (img + n * 784) : (lab + (n - N_IMG) * 784);
    __shared__ float sin_[32 * 32];
    __shared__ float sw[800];
    __shared__ float sb[32];
    int t = threadIdx.x;
    for (int idx = t; idx < 1024; idx += 256) {
        int y = idx >> 5, x = idx & 31;
        int iy = y - 2, ix = x - 2;
        float v = 0.f;
        if (iy >= 0 && iy < 28 && ix >= 0 && ix < 28) v = src[iy * 28 + ix];
        sin_[idx] = v;
    }
    for (int idx = t; idx < 800; idx += 256) sw[idx] = w[idx];
    if (t < 32) sb[t] = b[t];
    __syncthreads();
    int oc = t >> 3, tp = t & 7;
    float wr[25];
#pragma unroll
    for (int u = 0; u < 25; u++) wr[u] = sw[oc * 25 + u];
    float bias = sb[oc];
    for (int pos = tp; pos < 196; pos += 8) {
        int py = pos / 14, px = pos % 14;
        float win[36];
        int base = (2 * py) * 32 + 2 * px;
#pragma unroll
        for (int wy = 0; wy < 6; wy++)
#pragma unroll
            for (int wx = 0; wx < 6; wx++)
                win[wy * 6 + wx] = sin_[base + wy * 32 + wx];
        u64 pp[6][5];
#pragma unroll
        for (int ky = 0; ky < 6; ky++)
#pragma unroll
            for (int kx = 0; kx < 5; kx++) pp[ky][kx] = pk2(win[ky * 6 + kx], win[ky * 6 + kx + 1]);
        u64 A0 = 0ull, A1 = 0ull;
#pragma unroll
        for (int ky = 0; ky < 5; ky++)
#pragma unroll
            for (int kx = 0; kx < 5; kx++) {
                u64 wp = bc2(wr[ky * 5 + kx]);
                A0 = fma2(wp, pp[ky][kx], A0);
                A1 = fma2(wp, pp[ky + 1][kx], A1);
            }
        float2 f0 = up2(A0), f1 = up2(A1);
        float m = fmaxf(fmaxf(fmaxf(f0.x + bias, 0.f), fmaxf(f0.y + bias, 0.f)),
                        fmaxf(fmaxf(f1.x + bias, 0.f), fmaxf(f1.y + bias, 0.f)));
        d_pool1[n * 6272 + oc * 196 + pos] = m;
    }
}

// ---------------- conv2 + relu + pool : [N,32,14,14] -> [N,64,7,7] ---------
// R10 version (best measured: 537us). 392 thr = 49 pos x 8 oc-groups; weights
// read directly from pre-transposed d_w2[ic][k][oc] as warp-UNIFORM LDG.128.
__global__ void conv2_kernel(const float* __restrict__ b) {
    int n = blockIdx.x;
    __shared__ float sin_[32 * 18 * 18];  // 10368 floats
    int t = threadIdx.x;                  // 392 threads
    for (int idx = t; idx < 10368; idx += 392) {
        int ic = idx / 324, rem = idx % 324;
        int y = rem / 18, x = rem % 18;
        int iy = y - 2, ix = x - 2;
        float v = 0.f;
        if (iy >= 0 && iy < 14 && ix >= 0 && ix < 14)
            v = d_pool1[n * 6272 + ic * 196 + iy * 14 + ix];
        sin_[idx] = v;
    }
    __syncthreads();                      // the only barrier

    int pos = t % 49, grp = t / 49;       // 49 positions x 8 oc-groups
    int py = pos / 7, px = pos % 7;
    u64 acc[4][4];                        // [oc-pair][subpos 00,01,10,11]
#pragma unroll
    for (int p = 0; p < 4; p++)
#pragma unroll
        for (int q = 0; q < 4; q++) acc[p][q] = 0ull;

    const float* wg = d_w2 + grp * 8;     // [ic][k][oc] slice for this group
    for (int ic = 0; ic < 32; ic++) {
        float win[36];
        int base = ic * 324 + (2 * py) * 18 + 2 * px;   // even -> float2-aligned
#pragma unroll
        for (int wy = 0; wy < 6; wy++) {
            float2 va = *(const float2*)&sin_[base + wy * 18 + 0];
            float2 vb = *(const float2*)&sin_[base + wy * 18 + 2];
            float2 vc = *(const float2*)&sin_[base + wy * 18 + 4];
            win[wy * 6 + 0] = va.x; win[wy * 6 + 1] = va.y;
            win[wy * 6 + 2] = vb.x; win[wy * 6 + 3] = vb.y;
            win[wy * 6 + 4] = vc.x; win[wy * 6 + 5] = vc.y;
        }
        const float* wic = wg + ic * 1600;
#pragma unroll
        for (int ky = 0; ky < 5; ky++)
#pragma unroll
            for (int kx = 0; kx < 5; kx++) {
                const float* swk = wic + (ky * 5 + kx) * 64;   // 16B-aligned
                ulonglong2 wp01 = *(const ulonglong2*)&swk[0];
                ulonglong2 wp23 = *(const ulonglong2*)&swk[4];
                u64 wp0 = wp01.x, wp1 = wp01.y, wp2 = wp23.x, wp3 = wp23.y;
                u64 b00 = bc2(win[ky * 6 + kx]);
                u64 b01 = bc2(win[ky * 6 + kx + 1]);
                u64 b10 = bc2(win[(ky + 1) * 6 + kx]);
                u64 b11 = bc2(win[(ky + 1) * 6 + kx + 1]);
                acc[0][0] = fma2(wp0, b00, acc[0][0]);
                acc[0][1] = fma2(wp0, b01, acc[0][1]);
                acc[0][2] = fma2(wp0, b10, acc[0][2]);
                acc[0][3] = fma2(wp0, b11, acc[0][3]);
                acc[1][0] = fma2(wp1, b00, acc[1][0]);
                acc[1][1] = fma2(wp1, b01, acc[1][1]);
                acc[1][2] = fma2(wp1, b10, acc[1][2]);
                acc[1][3] = fma2(wp1, b11, acc[1][3]);
                acc[2][0] = fma2(wp2, b00, acc[2][0]);
                acc[2][1] = fma2(wp2, b01, acc[2][1]);
                acc[2][2] = fma2(wp2, b10, acc[2][2]);
                acc[2][3] = fma2(wp2, b11, acc[2][3]);
                acc[3][0] = fma2(wp3, b00, acc[3][0]);
                acc[3][1] = fma2(wp3, b01, acc[3][1]);
                acc[3][2] = fma2(wp3, b10, acc[3][2]);
                acc[3][3] = fma2(wp3, b11, acc[3][3]);
            }
    }
#pragma unroll
    for (int p = 0; p < 4; p++) {
        int oc0 = grp * 8 + 2 * p;
        float bias0 = b[oc0], bias1 = b[oc0 + 1];
        float2 v0 = up2(acc[p][0]), v1 = up2(acc[p][1]);
        float2 v2 = up2(acc[p][2]), v3 = up2(acc[p][3]);
        float m0 = fmaxf(fmaxf(fmaxf(v0.x + bias0, 0.f), fmaxf(v1.x + bias0, 0.f)),
                         fmaxf(fmaxf(v2.x + bias0, 0.f), fmaxf(v3.x + bias0, 0.f)));
        float m1 = fmaxf(fmaxf(fmaxf(v0.y + bias1, 0.f), fmaxf(v1.y + bias1, 0.f)),
                         fmaxf(fmaxf(v2.y + bias1, 0.f), fmaxf(v3.y + bias1, 0.f)));
        d_pool2[n * 3136 + oc0 * 49 + pos] = m0;
        d_pool2[n * 3136 + (oc0 + 1) * 49 + pos] = m1;
    }
}

// ---------------- fc1 (k-split x2): partials over K halves -----------------
// v4: 64x64 tile, 4x4/thread, double-buffered (R14) + gridDim.z=2 K-split.
// Each z-half accumulates k in ascending order over its 1568-wide range and
// writes a partial (no bias). fc1add combines: (p0 + p1) + bias.
__global__ void __launch_bounds__(256, 1) fc1_kernel(const float* __restrict__ fw) {
    __shared__ float As[2][32][66];
    __shared__ float Bs[2][32][66];
    int t = threadIdx.x;
    int tx = t & 15, ty = t >> 4;
    int m0 = blockIdx.x * 64;
    int n0 = blockIdx.y * 64;
    int ks = blockIdx.z * 1568;           // K half start
    float* pbuf = d_fcp + blockIdx.z * (N_TOT * LATENT);

    u64 acc[4][2];
#pragma unroll
    for (int i = 0; i < 4; i++) { acc[i][0] = 0ull; acc[i][1] = 0ull; }

    // ---- load tile kt=0 into buf 0
#pragma unroll
    for (int u = 0; u < 2; u++) {
        int id = t + u * 256;
        int row = id >> 3, k4 = id & 7;
        float4 va = *(const float4*)&d_pool2[(m0 + row) * 3136 + ks + k4 * 4];
        As[0][k4 * 4 + 0][row] = va.x;
        As[0][k4 * 4 + 1][row] = va.y;
        As[0][k4 * 4 + 2][row] = va.z;
        As[0][k4 * 4 + 3][row] = va.w;
        float4 vb = *(const float4*)&fw[(n0 + row) * 3136 + ks + k4 * 4];
        Bs[0][k4 * 4 + 0][row] = vb.x;
        Bs[0][k4 * 4 + 1][row] = vb.y;
        Bs[0][k4 * 4 + 2][row] = vb.z;
        Bs[0][k4 * 4 + 3][row] = vb.w;
    }
    __syncthreads();

    for (int kt = 0; kt < 49; kt++) {
        int cur = kt & 1;
        if (kt < 48) {                 // prefetch next tile into the other buf
            int nxt = cur ^ 1;
            int k0 = ks + (kt + 1) * 32;
#pragma unroll
            for (int u = 0; u < 2; u++) {
                int id = t + u * 256;
                int row = id >> 3, k4 = id & 7;
                float4 va = *(const float4*)&d_pool2[(m0 + row) * 3136 + k0 + k4 * 4];
                As[nxt][k4 * 4 + 0][row] = va.x;
                As[nxt][k4 * 4 + 1][row] = va.y;
                As[nxt][k4 * 4 + 2][row] = va.z;
                As[nxt][k4 * 4 + 3][row] = va.w;
                float4 vb = *(const float4*)&fw[(n0 + row) * 3136 + k0 + k4 * 4];
                Bs[nxt][k4 * 4 + 0][row] = vb.x;
                Bs[nxt][k4 * 4 + 1][row] = vb.y;
                Bs[nxt][k4 * 4 + 2][row] = vb.z;
                Bs[nxt][k4 * 4 + 3][row] = vb.w;
            }
        }
#pragma unroll
        for (int kk = 0; kk < 32; kk++) {
            u64 b01 = *(const u64*)&Bs[cur][kk][tx * 4];
            u64 b23 = *(const u64*)&Bs[cur][kk][tx * 4 + 2];
#pragma unroll
            for (int i = 0; i < 4; i++) {
                u64 ap = bc2(As[cur][kk][ty * 4 + i]);
                acc[i][0] = fma2(ap, b01, acc[i][0]);
                acc[i][1] = fma2(ap, b23, acc[i][1]);
            }
        }
        __syncthreads();               // next buf filled AND cur free for reuse
    }
#pragma unroll
    for (int i = 0; i < 4; i++) {
        int m = m0 + ty * 4 + i;
        float2 c01 = up2(acc[i][0]), c23 = up2(acc[i][1]);
        int nn = n0 + tx * 4;
        pbuf[m * 512 + nn + 0] = c01.x;
        pbuf[m * 512 + nn + 1] = c01.y;
        pbuf[m * 512 + nn + 2] = c23.x;
        pbuf[m * 512 + nn + 3] = c23.y;
    }
}

// ---------------- fc1 add: d_fc = (p0 + p1) + bias -------------------------
__global__ void fc1add_kernel(const float* __restrict__ fb) {
    int idx = blockIdx.x * 256 + threadIdx.x;       // 147456 float4s
    const float4* p0 = (const float4*)d_fcp;
    const float4* p1 = (const float4*)(d_fcp + N_TOT * LATENT);
    float4 a = p0[idx], b = p1[idx];
    int col = (idx & 127) * 4;                      // 128 float4 per row of 512
    float4 o;
    o.x = (a.x + b.x) + fb[col + 0];
    o.y = (a.y + b.y) + fb[col + 1];
    o.z = (a.z + b.z) + fb[col + 2];
    o.w = (a.w + b.w) + fb[col + 3];
    ((float4*)d_fc)[idx] = o;
}

// ---------------- rep = tanh(fc rows 1024..1151) + rho partial sums --------
__global__ void tanh_rep_kernel() {
    int bb = blockIdx.x;
    int t = threadIdx.x;
    float v = tanhf(d_fc[(N_IMG + bb) * LATENT + t]);
    d_rep[bb * LATENT + t] = v;
    float s = v;
#pragma unroll
    for (int off = 16; off > 0; off >>= 1) s += __shfl_down_sync(0xffffffffu, s, off);
    __shared__ float ws[16];
    if ((t & 31) == 0) ws[t >> 5] = s;
    __syncthreads();
    if (t == 0) {
        float tot = 0.f;
        for (int i = 0; i < 16; i++) tot += ws[i];
        d_rhopart[bb] = tot;
    }
}

__global__ void rho_kernel() {
    if (threadIdx.x == 0) {
        float s = 0.f;
        for (int i = 0; i < 128; i++) s += d_rhopart[i];
        d_rho[0] = s / 65536.0f;
    }
}

// ---------------- Hopfield W = ((rep-rho)^T (rep-rho)) * (1-I) / 128 -------
__global__ void hopw_kernel() {
    __shared__ float ti[128][32];
    __shared__ float tj[128][32];
    float rho = d_rho[0];
    int i0 = blockIdx.x * 32, j0 = blockIdx.y * 32;
    int t = threadIdx.x;
    for (int idx = t; idx < 4096; idx += 256) {
        int bb = idx >> 5, c = idx & 31;
        ti[bb][c] = d_rep[bb * 512 + i0 + c] - rho;
        tj[bb][c] = d_rep[bb * 512 + j0 + c] - rho;
    }
    __syncthreads();
    int tx = t & 15, ty = t >> 4;
    float a00 = 0.f, a01 = 0.f, a10 = 0.f, a11 = 0.f;
    for (int bb = 0; bb < 128; bb++) {
        float x0 = ti[bb][tx * 2], x1 = ti[bb][tx * 2 + 1];
        float y0 = tj[bb][ty * 2], y1 = tj[bb][ty * 2 + 1];
        a00 = fmaf(x0, y0, a00); a01 = fmaf(x0, y1, a01);
        a10 = fmaf(x1, y0, a10); a11 = fmaf(x1, y1, a11);
    }
    const float inv = 1.f / 128.f;
    int i = i0 + tx * 2, j = j0 + ty * 2;
    d_w[i * 512 + j]             = (i == j)         ? 0.f : a00 * inv;
    d_w[i * 512 + (j + 1)]       = (i == j + 1)     ? 0.f : a01 * inv;
    d_w[(i + 1) * 512 + j]       = (i + 1 == j)     ? 0.f : a10 * inv;
    d_w[(i + 1) * 512 + (j + 1)] = (i + 1 == j + 1) ? 0.f : a11 * inv;
}

// ---------------- label = softmax(lat @ fcn_w^T + fcn_b) -------------------
__global__ void label_kernel(const float* __restrict__ fw, const float* __restrict__ fb,
                             float* __restrict__ out) {
    int blk = blockIdx.x;          // images blk*4 .. blk*4+3
    int l = threadIdx.x;           // 0..127
    int lane = l & 31, warp = l >> 5;
    __shared__ float slat[4][512];
    __shared__ float redm[4], reds[4];
    for (int idx = l; idx < 512; idx += 128) {
        int img = idx >> 7, k4 = idx & 127;
        ((float4*)&slat[img][0])[k4] = ((const float4*)(d_fc + (blk * 4 + img) * 512))[k4];
    }
    __syncthreads();
    float acc[4];
    float bias = fb[l];
#pragma unroll
    for (int img = 0; img < 4; img++) acc[img] = bias;
    const float4* fr = (const float4*)(fw + l * 512);
    for (int kc = 0; kc < 16; kc++) {
        float4 wv[8];
#pragma unroll
        for (int c = 0; c < 8; c++) wv[c] = fr[kc * 8 + c];
#pragma unroll
        for (int img = 0; img < 4; img++) {
            const float4* s4 = (const float4*)&slat[img][kc * 32];
#pragma unroll
            for (int c = 0; c < 8; c++) {
                float4 sv = s4[c];
                acc[img] = fmaf(sv.x, wv[c].x, acc[img]);
                acc[img] = fmaf(sv.y, wv[c].y, acc[img]);
                acc[img] = fmaf(sv.z, wv[c].z, acc[img]);
                acc[img] = fmaf(sv.w, wv[c].w, acc[img]);
            }
        }
    }
    for (int img = 0; img < 4; img++) {
        float m = acc[img];
#pragma unroll
        for (int off = 16; off > 0; off >>= 1)
            m = fmaxf(m, __shfl_xor_sync(0xffffffffu, m, off));
        if (lane == 0) redm[warp] = m;
        __syncthreads();
        m = fmaxf(fmaxf(redm[0], redm[1]), fmaxf(redm[2], redm[3]));
        float ex = expf(acc[img] - m);
        float s = ex;
#pragma unroll
        for (int off = 16; off > 0; off >>= 1)
            s += __shfl_xor_sync(0xffffffffu, s, off);
        if (lane == 0) reds[warp] = s;
        __syncthreads();
        s = reds[0] + reds[1] + reds[2] + reds[3];
        out[131072 + (blk * 4 + img) * 128 + l] = ex / s;
        __syncthreads();
    }
}

// ---------------- Hopfield clustering (sparse union-delta) + softmax -------
__global__ void __launch_bounds__(512, 1) cluster_kernel(float* __restrict__ out) {
    __shared__ float coef[512][8];
    __shared__ int   ulist[512];
    __shared__ int   warpcnt[16], warpbase[16];
    __shared__ int   s_nf, doneflag;
    __shared__ float epart[16][8];
    __shared__ float esm[8];
    __shared__ unsigned wA[16], wB[16];
    __shared__ float dots[8][128];

    int t = threadIdx.x;
    int lane = t & 31, warp = t >> 5;
    int row0 = blockIdx.x * 8;
    const float* wc = d_w + t;

    float h[8], sp[8], sp2[8], mins[8], min_e[8];
    const float nanv = __int_as_float(0x7fffffff);

#pragma unroll
    for (int r = 0; r < 8; r++) {
        float v = tanhf(d_fc[(row0 + r) * 512 + t]);
        sp[r] = v;
        sp2[r] = nanv;
        mins[r] = 0.f;
        min_e[r] = INFINITY;
    }
    *(float4*)&coef[t][0] = make_float4(sp[0], sp[1], sp[2], sp[3]);
    *(float4*)&coef[t][4] = make_float4(sp[4], sp[5], sp[6], sp[7]);
    __syncthreads();

    // prologue full GEMV: h = s0 @ w
    {
        u64 hh[4] = {0ull, 0ull, 0ull, 0ull};
#pragma unroll 4
        for (int j = 0; j < 512; j++) {
            u64 wp = bc2(wc[j * 512]);
            ulonglong2 cA = *(const ulonglong2*)&coef[j][0];
            ulonglong2 cB = *(const ulonglong2*)&coef[j][4];
            hh[0] = fma2(wp, cA.x, hh[0]);
            hh[1] = fma2(wp, cA.y, hh[1]);
            hh[2] = fma2(wp, cB.x, hh[2]);
            hh[3] = fma2(wp, cB.y, hh[3]);
        }
#pragma unroll
        for (int q = 0; q < 4; q++) {
            float2 f = up2(hh[q]);
            h[2 * q] = f.x; h[2 * q + 1] = f.y;
        }
    }

    for (int iter = 0; iter < LATENT; iter++) {
        float sn[8], cf[8];
        unsigned a = 0, b = 0;
        bool flip = false;
#pragma unroll
        for (int r = 0; r < 8; r++) {
            float v = fabsf(sp[r]) * sgnf(h[r]);
            sn[r] = v;
            cf[r] = v - sp[r];
            if (cf[r] != 0.f) flip = true;
            if (v == sp[r]) a |= (1u << r);
            if (v == sp2[r]) b |= (1u << r);
        }
        a = __reduce_and_sync(0xffffffffu, a);
        b = __reduce_and_sync(0xffffffffu, b);
        unsigned bal = __ballot_sync(0xffffffffu, flip);
        if (lane == 0) { wA[warp] = a; wB[warp] = b; warpcnt[warp] = __popc(bal); }
        __syncthreads();   // S1
        *(float4*)&coef[t][0] = make_float4(cf[0], cf[1], cf[2], cf[3]);
        *(float4*)&coef[t][4] = make_float4(cf[4], cf[5], cf[6], cf[7]);
        if (t == 0) {
            int accn = 0;
            unsigned A = 0xffu, B = 0xffu;
            for (int q = 0; q < 16; q++) {
                warpbase[q] = accn;
                accn += warpcnt[q];
                A &= wA[q]; B &= wB[q];
            }
            s_nf = accn;
            doneflag = ((A | B) == 0xffu) ? 1 : 0;
        }
        __syncthreads();   // S2
        if (flip) {
            int rank = __popc(bal & ((1u << lane) - 1u));
            ulist[warpbase[warp] + rank] = t;
        }
        __syncthreads();   // S3
        int nf = s_nf;
        int done = doneflag;

        // delta update: h += coef[j] * w[j][t] over union list
        {
            u64 hh[4];
#pragma unroll
            for (int q = 0; q < 4; q++) hh[q] = pk2(h[2 * q], h[2 * q + 1]);
            int i = 0;
            for (; i + 4 <= nf; i += 4) {
                int j0 = ulist[i], j1 = ulist[i + 1], j2 = ulist[i + 2], j3 = ulist[i + 3];
                float w0 = wc[j0 * 512], w1 = wc[j1 * 512];
                float w2 = wc[j2 * 512], w3 = wc[j3 * 512];
                {
                    u64 wp = bc2(w0);
                    ulonglong2 cA = *(const ulonglong2*)&coef[j0][0];
                    ulonglong2 cB = *(const ulonglong2*)&coef[j0][4];
                    hh[0] = fma2(wp, cA.x, hh[0]); hh[1] = fma2(wp, cA.y, hh[1]);
                    hh[2] = fma2(wp, cB.x, hh[2]); hh[3] = fma2(wp, cB.y, hh[3]);
                }
                {
                    u64 wp = bc2(w1);
                    ulonglong2 cA = *(const ulonglong2*)&coef[j1][0];
                    ulonglong2 cB = *(const ulonglong2*)&coef[j1][4];
                    hh[0] = fma2(wp, cA.x, hh[0]); hh[1] = fma2(wp, cA.y, hh[1]);
                    hh[2] = fma2(wp, cB.x, hh[2]); hh[3] = fma2(wp, cB.y, hh[3]);
                }
                {
                    u64 wp = bc2(w2);
                    ulonglong2 cA = *(const ulonglong2*)&coef[j2][0];
                    ulonglong2 cB = *(const ulonglong2*)&coef[j2][4];
                    hh[0] = fma2(wp, cA.x, hh[0]); hh[1] = fma2(wp, cA.y, hh[1]);
                    hh[2] = fma2(wp, cB.x, hh[2]); hh[3] = fma2(wp, cB.y, hh[3]);
                }
                {
                    u64 wp = bc2(w3);
                    ulonglong2 cA = *(const ulonglong2*)&coef[j3][0];
                    ulonglong2 cB = *(const ulonglong2*)&coef[j3][4];
                    hh[0] = fma2(wp, cA.x, hh[0]); hh[1] = fma2(wp, cA.y, hh[1]);
                    hh[2] = fma2(wp, cB.x, hh[2]); hh[3] = fma2(wp, cB.y, hh[3]);
                }
            }
            for (; i < nf; i++) {
                int j = ulist[i];
                u64 wp = bc2(wc[j * 512]);
                ulonglong2 cA = *(const ulonglong2*)&coef[j][0];
                ulonglong2 cB = *(const ulonglong2*)&coef[j][4];
                hh[0] = fma2(wp, cA.x, hh[0]); hh[1] = fma2(wp, cA.y, hh[1]);
                hh[2] = fma2(wp, cB.x, hh[2]); hh[3] = fma2(wp, cB.y, hh[3]);
            }
#pragma unroll
            for (int q = 0; q < 4; q++) {
                float2 f = up2(hh[q]);
                h[2 * q] = f.x; h[2 * q + 1] = f.y;
            }
        }

        // energy e[r] = -sum_t sn[r]*h[r]
        float p[8];
#pragma unroll
        for (int r = 0; r < 8; r++) p[r] = sn[r] * h[r];
#pragma unroll
        for (int r = 0; r < 8; r++) {
#pragma unroll
            for (int off = 16; off > 0; off >>= 1)
                p[r] += __shfl_down_sync(0xffffffffu, p[r], off);
        }
        if (lane == 0) {
#pragma unroll
            for (int r = 0; r < 8; r++) epart[warp][r] = p[r];
        }
        __syncthreads();   // S4
        if (t < 8) {
            float e = 0.f;
            for (int q = 0; q < 16; q++) e += epart[q][t];
            esm[t] = -e;
        }
        __syncthreads();   // S5
#pragma unroll
        for (int r = 0; r < 8; r++) {
            float e = esm[r];
            if (e < min_e[r]) { min_e[r] = e; mins[r] = sn[r]; }
            sp2[r] = sp[r]; sp[r] = sn[r];
        }
        if (done) break;
    }

    // ---------------- epilogue: out = softmax(|min_s @ rep^T|) -------------
    __syncthreads();
    *(float4*)&coef[t][0] = make_float4(mins[0], mins[1], mins[2], mins[3]);
    *(float4*)&coef[t][4] = make_float4(mins[4], mins[5], mins[6], mins[7]);
    __syncthreads();

    int l = t >> 2, q = t & 3;
#pragma unroll
    for (int r = 0; r < 8; r++) {
        const float4* rp = (const float4*)(d_rep + l * 512 + q * 128);
        float v = 0.f;
#pragma unroll 8
        for (int i4 = 0; i4 < 32; i4++) {
            float4 rv = rp[i4];
            int j = q * 128 + i4 * 4;
            v = fmaf(coef[j + 0][r], rv.x, v);
            v = fmaf(coef[j + 1][r], rv.y, v);
            v = fmaf(coef[j + 2][r], rv.z, v);
            v = fmaf(coef[j + 3][r], rv.w, v);
        }
        v += __shfl_xor_sync(0xffffffffu, v, 1);
        v += __shfl_xor_sync(0xffffffffu, v, 2);
        if (q == 0) dots[r][l] = fabsf(v);
    }
    __syncthreads();

    if (warp < 8) {
        int r = warp;
        float v0 = dots[r][lane], v1 = dots[r][lane + 32];
        float v2 = dots[r][lane + 64], v3 = dots[r][lane + 96];
        float m = fmaxf(fmaxf(v0, v1), fmaxf(v2, v3));
#pragma unroll
        for (int off = 16; off > 0; off >>= 1)
            m = fmaxf(m, __shfl_xor_sync(0xffffffffu, m, off));
        float e0 = expf(v0 - m), e1 = expf(v1 - m), e2 = expf(v2 - m), e3 = expf(v3 - m);
        float s = e0 + e1 + e2 + e3;
#pragma unroll
        for (int off = 16; off > 0; off >>= 1)
            s += __shfl_xor_sync(0xffffffffu, s, off);
        float inv = 1.f / s;
        float* o = out + (row0 + r) * 128;
        o[lane] = e0 * inv;
        o[lane + 32] = e1 * inv;
        o[lane + 64] = e2 * inv;
        o[lane + 96] = e3 * inv;
    }
}

// ---------------------------------------------------------------------------
extern "C" void kernel_launch(void* const* d_in, const int* in_sizes, int n_in,
                              void* d_out, int out_size) {
    const float* image     = (const float*)d_in[0];
    const float* label_img = (const float*)d_in[1];
    const float* c1w       = (const float*)d_in[2];
    const float* c1b       = (const float*)d_in[3];
    const float* c2w       = (const float*)d_in[4];
    const float* c2b       = (const float*)d_in[5];
    const float* f1w       = (const float*)d_in[6];
    const float* f1b       = (const float*)d_in[7];
    const float* fnw       = (const float*)d_in[8];
    const float* fnb       = (const float*)d_in[9];
    float* out = (float*)d_out;

    // launch index 3 is the ncu-profiled slot -> fc1 (k-split) this round
    transpose_w2_kernel<<<200, 256>>>(c2w);               // 0
    conv1_kernel<<<N_TOT, 256>>>(image, label_img, c1w, c1b); // 1
    conv2_kernel<<<N_TOT, 392>>>(c2b);                    // 2
    fc1_kernel<<<dim3(18, 8, 2), 256>>>(f1w);             // 3  <- profiled (288 CTAs)
    fc1add_kernel<<<576, 256>>>(f1b);                     // 4
    label_kernel<<<256, 128>>>(fnw, fnb, out);
    tanh_rep_kernel<<<128, 512>>>();
    rho_kernel<<<1, 32>>>();
    hopw_kernel<<<dim3(16, 16), 256>>>();
    cluster_kernel<<<128, 512>>>(out);
}